// round 10
// baseline (speedup 1.0000x reference)
#include <cuda_runtime.h>
#include <cuda_bf16.h>
#include <cstdint>
#include <math.h>

// ---------------- problem constants ----------------
#define NSEQ   512
#define LSEQ   64
#define MDIM   (NSEQ*LSEQ)  // 32768
#define CDIM   256
#define DI     512
#define NXZ    1024
#define DST    16
#define DTR    16
#define NXP    48

// ---------------- scratch (device symbols: referenced ONLY inside device code) ----------------
__device__ float g_xz [MDIM * NXZ];     // 134 MB
__device__ float g_xc [MDIM * DI];      // 67 MB
__device__ float g_dbc[MDIM * NXP];     // 6.3 MB
__device__ float g_y  [MDIM * DI];      // 67 MB (scan out, includes +xc*D)
__device__ float g_tmp[MDIM * CDIM];    // 33.5 MB
__device__ float g_xT [8 * 256 * 64 * 64];
__device__ __nv_bfloat16 g_ah [MDIM * 256];
__device__ __nv_bfloat16 g_al [MDIM * 256];
__device__ __nv_bfloat16 g_yh [MDIM * DI];
__device__ __nv_bfloat16 g_yl [MDIM * DI];
__device__ __nv_bfloat16 g_wtih[1024 * 256];
__device__ __nv_bfloat16 g_wtil[1024 * 256];
__device__ __nv_bfloat16 g_wtoh[256 * 512];
__device__ __nv_bfloat16 g_wtol[256 * 512];

__device__ __forceinline__ float siluf(float v)    { return v / (1.f + __expf(-v)); }
__device__ __forceinline__ float softplusf(float v){ return (v > 20.f) ? v : log1pf(expf(v)); }

// ---------------- mma.sync / cp.async helpers ----------------
__device__ __forceinline__ void mma16816(float* c, const uint32_t* a, const uint32_t* b) {
    asm volatile(
        "mma.sync.aligned.m16n8k16.row.col.f32.bf16.bf16.f32 "
        "{%0,%1,%2,%3}, {%4,%5,%6,%7}, {%8,%9}, {%0,%1,%2,%3};\n"
        : "+f"(c[0]), "+f"(c[1]), "+f"(c[2]), "+f"(c[3])
        : "r"(a[0]), "r"(a[1]), "r"(a[2]), "r"(a[3]), "r"(b[0]), "r"(b[1]));
}
__device__ __forceinline__ void cp16(uint32_t saddr, const void* g) {
    asm volatile("cp.async.cg.shared.global [%0], [%1], 16;" :: "r"(saddr), "l"(g));
}
#define CP_COMMIT() asm volatile("cp.async.commit_group;" ::: "memory")
#define CP_WAIT(n)  asm volatile("cp.async.wait_group %0;" :: "n"(n) : "memory")

// ---------------- transpose x(b,c,h,w) -> xT(b,c,w,h) ----------------
__global__ void k_transpose_hw(const float* __restrict__ x) {
    __shared__ float tile[32][33];
    int bc = blockIdx.z, ht = blockIdx.y, wt = blockIdx.x;
    const float* src = x    + (size_t)bc * 4096;
    float*       dst = g_xT + (size_t)bc * 4096;
    int tx = threadIdx.x, ty = threadIdx.y;
    #pragma unroll
    for (int i = 0; i < 4; i++) {
        int h = ht * 32 + ty + i * 8;
        tile[ty + i * 8][tx] = src[h * 64 + wt * 32 + tx];
    }
    __syncthreads();
    #pragma unroll
    for (int i = 0; i < 4; i++) {
        int w = wt * 32 + ty + i * 8;
        dst[w * 64 + ht * 32 + tx] = tile[tx][ty + i * 8];
    }
}

// ---------------- convert A: src[(b*256+k)*4096+rem] -> bf16 hi/lo [m][k] ----------------
__global__ void k_convA(const float* __restrict__ xin, int useT) {
    __shared__ float t[32][33];
    const float* src = useT ? g_xT : xin;
    int b = blockIdx.z, kt = blockIdx.y, rt = blockIdx.x;
    int tx = threadIdx.x, ty = threadIdx.y;
    #pragma unroll
    for (int i = 0; i < 4; i++) {
        int k = kt * 32 + ty + i * 8;
        t[ty + i * 8][tx] = src[(size_t)(b * 256 + k) * 4096 + rt * 32 + tx];
    }
    __syncthreads();
    #pragma unroll
    for (int i = 0; i < 4; i++) {
        int rem = rt * 32 + ty + i * 8;
        size_t m = (size_t)b * 4096 + rem;
        float v = t[tx][ty + i * 8];
        __nv_bfloat16 h = __float2bfloat16(v);
        g_ah[m * 256 + kt * 32 + tx] = h;
        g_al[m * 256 + kt * 32 + tx] = __float2bfloat16(v - __bfloat162float(h));
    }
}

// ---------------- convert+transpose weights: W[R,C] fp32 -> T[C,R] bf16 hi/lo ----------------
__global__ void k_convW(const float* __restrict__ W, int R, int C, int which) {
    __shared__ float t[32][33];
    __nv_bfloat16* Th = which ? g_wtoh : g_wtih;
    __nv_bfloat16* Tl = which ? g_wtol : g_wtil;
    int r0 = blockIdx.y * 32, c0 = blockIdx.x * 32;
    int tx = threadIdx.x, ty = threadIdx.y;
    #pragma unroll
    for (int i = 0; i < 4; i++)
        t[ty + i * 8][tx] = W[(size_t)(r0 + ty + i * 8) * C + c0 + tx];
    __syncthreads();
    #pragma unroll
    for (int i = 0; i < 4; i++) {
        float v = t[tx][ty + i * 8];
        int oc = c0 + ty + i * 8;
        __nv_bfloat16 h = __float2bfloat16(v);
        Th[(size_t)oc * R + r0 + tx] = h;
        Tl[(size_t)oc * R + r0 + tx] = __float2bfloat16(v - __bfloat162float(h));
    }
}

// ---------------- shared GEMM config ----------------
__device__ __forceinline__ void gemm_cfg(int mode, const __nv_bfloat16*& Ah,
    const __nv_bfloat16*& Al, const __nv_bfloat16*& Bh, const __nv_bfloat16*& Bl,
    float*& Cout, int& K, int& ldc)
{
    if (mode == 0) { Ah = g_ah; Al = g_al; Bh = g_wtih; Bl = g_wtil; Cout = g_xz;  K = 256; ldc = NXZ; }
    else           { Ah = g_yh; Al = g_yl; Bh = g_wtoh; Bl = g_wtol; Cout = g_tmp; K = 512; ldc = CDIM; }
}

__device__ __forceinline__ void gemm_epilogue(float acc[4][4][4], float* Cout, int ldc,
                                              int m0, int n0, int wr, int wc, int g, int tg)
{
    #pragma unroll
    for (int mt = 0; mt < 4; mt++)
        #pragma unroll
        for (int nt = 0; nt < 4; nt++) {
            int row = m0 + wr * 64 + mt * 16 + g;
            int col = n0 + wc * 32 + nt * 8 + tg * 2;
            *(float2*)&Cout[(size_t)row * ldc + col] =
                make_float2(acc[mt][nt][0], acc[mt][nt][1]);
            *(float2*)&Cout[(size_t)(row + 8) * ldc + col] =
                make_float2(acc[mt][nt][2], acc[mt][nt][3]);
        }
}

// ---------------- HMMA bf16x3 GEMM, BK=32, cp.async 2-stage, DYNAMIC smem ----------------
#define SSTR32 40
#define TILE32 (128 * SSTR32)
#define STG32  (4 * TILE32)
__global__ void __launch_bounds__(256, 2) k_mma_gemm32(int mode) {
    extern __shared__ __nv_bfloat16 dsm[];

    const __nv_bfloat16 *Ah, *Al, *Bh, *Bl;
    float* Cout; int K, ldc;
    gemm_cfg(mode, Ah, Al, Bh, Bl, Cout, K, ldc);

    int tid = threadIdx.x, warp = tid >> 5, lane = tid & 31;
    int wr = warp >> 2, wc = warp & 3;
    int g = lane >> 2, tg = lane & 3;
    int m0 = blockIdx.y * 128, n0 = blockIdx.x * 128;

    const __nv_bfloat16* base0 = Ah + (size_t)m0 * K;
    const __nv_bfloat16* base1 = Al + (size_t)m0 * K;
    const __nv_bfloat16* base2 = Bh + (size_t)n0 * K;
    const __nv_bfloat16* base3 = Bl + (size_t)n0 * K;

    uint32_t sbase = (uint32_t)__cvta_generic_to_shared(dsm);
    float acc[4][4][4];
    #pragma unroll
    for (int i = 0; i < 4; i++)
        #pragma unroll
        for (int j = 0; j < 4; j++)
            #pragma unroll
            for (int q = 0; q < 4; q++) acc[i][j][q] = 0.f;

    #pragma unroll
    for (int i = 0; i < 2; i++) {
        int idx = tid + i * 256;
        int r = idx >> 2, q = idx & 3;
        size_t go = (size_t)r * K + q * 8;
        uint32_t so = sbase + (uint32_t)(r * SSTR32 + q * 8) * 2;
        cp16(so + 0 * TILE32 * 2, base0 + go);
        cp16(so + 1 * TILE32 * 2, base1 + go);
        cp16(so + 2 * TILE32 * 2, base2 + go);
        cp16(so + 3 * TILE32 * 2, base3 + go);
    }
    CP_COMMIT();

    const int T = K >> 5;
    for (int it = 0; it < T; it++) {
        if (it + 1 < T) {
            int k0n = (it + 1) << 5;
            uint32_t sb = sbase + ((it + 1) & 1) * STG32 * 2;
            #pragma unroll
            for (int i = 0; i < 2; i++) {
                int idx = tid + i * 256;
                int r = idx >> 2, q = idx & 3;
                size_t go = (size_t)r * K + q * 8 + k0n;
                uint32_t so = sb + (uint32_t)(r * SSTR32 + q * 8) * 2;
                cp16(so + 0 * TILE32 * 2, base0 + go);
                cp16(so + 1 * TILE32 * 2, base1 + go);
                cp16(so + 2 * TILE32 * 2, base2 + go);
                cp16(so + 3 * TILE32 * 2, base3 + go);
            }
            CP_COMMIT();
            CP_WAIT(1);
        } else {
            CP_WAIT(0);
        }
        __syncthreads();

        const __nv_bfloat16* s0  = dsm + (it & 1) * STG32;
        const __nv_bfloat16* sAh = s0;
        const __nv_bfloat16* sAl = s0 + TILE32;
        const __nv_bfloat16* sBh = s0 + 2 * TILE32;
        const __nv_bfloat16* sBl = s0 + 3 * TILE32;

        #pragma unroll
        for (int ks = 0; ks < 2; ks++) {
            int kb = ks * 16 + tg * 2;
            uint32_t a_hi[4][4], a_lo[4][4], b_hi[4][2], b_lo[4][2];
            #pragma unroll
            for (int mt = 0; mt < 4; mt++) {
                int row = wr * 64 + mt * 16 + g;
                a_hi[mt][0] = *(const uint32_t*)&sAh[row * SSTR32 + kb];
                a_hi[mt][1] = *(const uint32_t*)&sAh[(row + 8) * SSTR32 + kb];
                a_hi[mt][2] = *(const uint32_t*)&sAh[row * SSTR32 + kb + 8];
                a_hi[mt][3] = *(const uint32_t*)&sAh[(row + 8) * SSTR32 + kb + 8];
                a_lo[mt][0] = *(const uint32_t*)&sAl[row * SSTR32 + kb];
                a_lo[mt][1] = *(const uint32_t*)&sAl[(row + 8) * SSTR32 + kb];
                a_lo[mt][2] = *(const uint32_t*)&sAl[row * SSTR32 + kb + 8];
                a_lo[mt][3] = *(const uint32_t*)&sAl[(row + 8) * SSTR32 + kb + 8];
            }
            #pragma unroll
            for (int nt = 0; nt < 4; nt++) {
                int rn = wc * 32 + nt * 8 + g;
                b_hi[nt][0] = *(const uint32_t*)&sBh[rn * SSTR32 + kb];
                b_hi[nt][1] = *(const uint32_t*)&sBh[rn * SSTR32 + kb + 8];
                b_lo[nt][0] = *(const uint32_t*)&sBl[rn * SSTR32 + kb];
                b_lo[nt][1] = *(const uint32_t*)&sBl[rn * SSTR32 + kb + 8];
            }
            #pragma unroll
            for (int mt = 0; mt < 4; mt++)
                #pragma unroll
                for (int nt = 0; nt < 4; nt++) {
                    mma16816(acc[mt][nt], a_hi[mt], b_hi[nt]);
                    mma16816(acc[mt][nt], a_hi[mt], b_lo[nt]);
                    mma16816(acc[mt][nt], a_lo[mt], b_hi[nt]);
                }
        }
        __syncthreads();
    }
    gemm_epilogue(acc, Cout, ldc, m0, n0, wr, wc, g, tg);
}

// ---------------- fallback: BK=16, static smem ----------------
#define SSTR 24
#define TILE_E (128 * SSTR)
#define STAGE_E (4 * TILE_E)
__global__ void __launch_bounds__(256, 2) k_mma_gemm16(int mode) {
    __shared__ __align__(16) __nv_bfloat16 smem[2 * STAGE_E];

    const __nv_bfloat16 *Ah, *Al, *Bh, *Bl;
    float* Cout; int K, ldc;
    gemm_cfg(mode, Ah, Al, Bh, Bl, Cout, K, ldc);

    int tid = threadIdx.x, warp = tid >> 5, lane = tid & 31;
    int wr = warp >> 2, wc = warp & 3;
    int g = lane >> 2, tg = lane & 3;
    int m0 = blockIdx.y * 128, n0 = blockIdx.x * 128;

    const __nv_bfloat16* base0 = Ah + (size_t)m0 * K;
    const __nv_bfloat16* base1 = Al + (size_t)m0 * K;
    const __nv_bfloat16* base2 = Bh + (size_t)n0 * K;
    const __nv_bfloat16* base3 = Bl + (size_t)n0 * K;

    uint32_t sbase = (uint32_t)__cvta_generic_to_shared(smem);
    int lr = tid >> 1, lq = tid & 1;
    size_t goff = (size_t)lr * K + lq * 8;
    uint32_t soff = (uint32_t)(lr * SSTR + lq * 8) * 2;

    float acc[4][4][4];
    #pragma unroll
    for (int i = 0; i < 4; i++)
        #pragma unroll
        for (int j = 0; j < 4; j++)
            #pragma unroll
            for (int q = 0; q < 4; q++) acc[i][j][q] = 0.f;

    {
        uint32_t sb = sbase + soff;
        cp16(sb + 0 * TILE_E * 2, base0 + goff);
        cp16(sb + 1 * TILE_E * 2, base1 + goff);
        cp16(sb + 2 * TILE_E * 2, base2 + goff);
        cp16(sb + 3 * TILE_E * 2, base3 + goff);
        CP_COMMIT();
    }

    const int T = K >> 4;
    for (int it = 0; it < T; it++) {
        if (it + 1 < T) {
            int k0n = (it + 1) << 4;
            uint32_t sb = sbase + ((it + 1) & 1) * STAGE_E * 2 + soff;
            cp16(sb + 0 * TILE_E * 2, base0 + goff + k0n);
            cp16(sb + 1 * TILE_E * 2, base1 + goff + k0n);
            cp16(sb + 2 * TILE_E * 2, base2 + goff + k0n);
            cp16(sb + 3 * TILE_E * 2, base3 + goff + k0n);
            CP_COMMIT();
            CP_WAIT(1);
        } else {
            CP_WAIT(0);
        }
        __syncthreads();

        const __nv_bfloat16* s0 = smem + (it & 1) * STAGE_E;
        const __nv_bfloat16* sAh = s0;
        const __nv_bfloat16* sAl = s0 + TILE_E;
        const __nv_bfloat16* sBh = s0 + 2 * TILE_E;
        const __nv_bfloat16* sBl = s0 + 3 * TILE_E;
        int kb = tg * 2;

        uint32_t a_hi[4][4], a_lo[4][4], b_hi[4][2], b_lo[4][2];
        #pragma unroll
        for (int mt = 0; mt < 4; mt++) {
            int row = wr * 64 + mt * 16 + g;
            a_hi[mt][0] = *(const uint32_t*)&sAh[row * SSTR + kb];
            a_hi[mt][1] = *(const uint32_t*)&sAh[(row + 8) * SSTR + kb];
            a_hi[mt][2] = *(const uint32_t*)&sAh[row * SSTR + kb + 8];
            a_hi[mt][3] = *(const uint32_t*)&sAh[(row + 8) * SSTR + kb + 8];
            a_lo[mt][0] = *(const uint32_t*)&sAl[row * SSTR + kb];
            a_lo[mt][1] = *(const uint32_t*)&sAl[(row + 8) * SSTR + kb];
            a_lo[mt][2] = *(const uint32_t*)&sAl[row * SSTR + kb + 8];
            a_lo[mt][3] = *(const uint32_t*)&sAl[(row + 8) * SSTR + kb + 8];
        }
        #pragma unroll
        for (int nt = 0; nt < 4; nt++) {
            int rn = wc * 32 + nt * 8 + g;
            b_hi[nt][0] = *(const uint32_t*)&sBh[rn * SSTR + kb];
            b_hi[nt][1] = *(const uint32_t*)&sBh[rn * SSTR + kb + 8];
            b_lo[nt][0] = *(const uint32_t*)&sBl[rn * SSTR + kb];
            b_lo[nt][1] = *(const uint32_t*)&sBl[rn * SSTR + kb + 8];
        }
        #pragma unroll
        for (int mt = 0; mt < 4; mt++)
            #pragma unroll
            for (int nt = 0; nt < 4; nt++) {
                mma16816(acc[mt][nt], a_hi[mt], b_hi[nt]);
                mma16816(acc[mt][nt], a_hi[mt], b_lo[nt]);
                mma16816(acc[mt][nt], a_lo[mt], b_hi[nt]);
            }
        __syncthreads();
    }
    gemm_epilogue(acc, Cout, ldc, m0, n0, wr, wc, g, tg);
}

// ---------------- depthwise conv(4, causal) + bias + silu ----------------
__global__ void k_conv_silu(const float* __restrict__ cw, const float* __restrict__ cb) {
    int s = blockIdx.x;
    int d = blockIdx.y * 128 + threadIdx.x;
    float w0 = cw[d * 4 + 0], w1 = cw[d * 4 + 1], w2 = cw[d * 4 + 2], w3 = cw[d * 4 + 3];
    float bias = cb[d];
    float x0 = 0.f, x1 = 0.f, x2 = 0.f;
    const float* xp = g_xz + (size_t)s * LSEQ * NXZ + d;
    float*       op = g_xc + (size_t)s * LSEQ * DI  + d;
    #pragma unroll 4
    for (int t = 0; t < LSEQ; t++) {
        float x3 = xp[t * NXZ];
        float a = fmaf(w3, x3, fmaf(w2, x2, fmaf(w1, x1, fmaf(w0, x0, bias))));
        op[t * DI] = siluf(a);
        x0 = x1; x1 = x2; x2 = x3;
    }
}

// ---------------- x-proj GEMM: g_dbc[m, 0:48] = g_xc[m,:] @ W_xproj ----------------
// Register-blocked 4 rows x 3 cols per thread: per k = 1 LDS.128 + 3 LDS vs 12 FMA.
__global__ void __launch_bounds__(256) k_xproj(const float* __restrict__ Wx) {
    __shared__ __align__(16) float As[32][68];   // stride 68: 272B rows, 16B aligned
    __shared__ float Bs[32][48];
    int m0 = blockIdx.x * 64;
    int tid = threadIdx.x;
    int rg = tid & 15;          // rows rg*4 .. rg*4+3
    int cg = tid >> 4;          // cols cg*3 .. cg*3+2
    float acc[4][3];
    #pragma unroll
    for (int i = 0; i < 4; i++)
        #pragma unroll
        for (int j = 0; j < 3; j++) acc[i][j] = 0.f;

    for (int k0 = 0; k0 < DI; k0 += 32) {
        #pragma unroll
        for (int i = 0; i < 2; i++) {
            int idx = tid + i * 256;             // 0..511
            int r = idx >> 3, kc = (idx & 7) * 4;
            float4 v = *(const float4*)&g_xc[(size_t)(m0 + r) * DI + k0 + kc];
            As[kc + 0][r] = v.x; As[kc + 1][r] = v.y;
            As[kc + 2][r] = v.z; As[kc + 3][r] = v.w;
        }
        #pragma unroll
        for (int i = 0; i < 6; i++) {
            int idx = tid + i * 256;
            int k = idx / 48, n = idx % 48;
            Bs[k][n] = Wx[(k0 + k) * NXP + n];
        }
        __syncthreads();
        #pragma unroll
        for (int k = 0; k < 32; k++) {
            float4 a = *(const float4*)&As[k][rg * 4];
            float b0 = Bs[k][cg * 3 + 0];
            float b1 = Bs[k][cg * 3 + 1];
            float b2 = Bs[k][cg * 3 + 2];
            acc[0][0] = fmaf(a.x, b0, acc[0][0]);
            acc[0][1] = fmaf(a.x, b1, acc[0][1]);
            acc[0][2] = fmaf(a.x, b2, acc[0][2]);
            acc[1][0] = fmaf(a.y, b0, acc[1][0]);
            acc[1][1] = fmaf(a.y, b1, acc[1][1]);
            acc[1][2] = fmaf(a.y, b2, acc[1][2]);
            acc[2][0] = fmaf(a.z, b0, acc[2][0]);
            acc[2][1] = fmaf(a.z, b1, acc[2][1]);
            acc[2][2] = fmaf(a.z, b2, acc[2][2]);
            acc[3][0] = fmaf(a.w, b0, acc[3][0]);
            acc[3][1] = fmaf(a.w, b1, acc[3][1]);
            acc[3][2] = fmaf(a.w, b2, acc[3][2]);
        }
        __syncthreads();
    }
    #pragma unroll
    for (int i = 0; i < 4; i++)
        #pragma unroll
        for (int j = 0; j < 3; j++)
            g_dbc[(size_t)(m0 + rg * 4 + i) * NXP + cg * 3 + j] = acc[i][j];
}

// ---------------- selective scan (dt-proj fused; exp-recurrence; writes y+xc*D) ----------------
__global__ void __launch_bounds__(512) k_scan(const float* __restrict__ Alog,
                                              const float* __restrict__ Wdt,
                                              const float* __restrict__ bdt,
                                              const float* __restrict__ Dp) {
    __shared__ float Rs[LSEQ][DTR];
    __shared__ float Bs[LSEQ][DST];
    __shared__ float Cs[LSEQ][DST];
    int s = blockIdx.x;
    int d = threadIdx.x;
    for (int i = threadIdx.x; i < LSEQ * NXP; i += 512) {
        int t = i / NXP, j = i % NXP;
        float v = g_dbc[(size_t)(s * LSEQ + t) * NXP + j];
        if (j < DTR) Rs[t][j] = v;
        else if (j < DTR + DST) Bs[t][j - DTR] = v;
        else Cs[t][j - DTR - DST] = v;
    }
    __syncthreads();
    float A[DST], h[DST], w[DTR];
    bool fast = true;
    #pragma unroll
    for (int n = 0; n < DST; n++) {
        A[n] = -expf(Alog[d * DST + n]);
        h[n] = 0.f;
        fast = fast && (fabsf(A[n] + (float)(n + 1)) <= 1e-3f * (float)(n + 1));
    }
    #pragma unroll
    for (int i = 0; i < DTR; i++) w[i] = Wdt[i * DI + d];
    float bd = bdt[d];
    float Dd = Dp[d];
    const float* xp = g_xc + (size_t)s * LSEQ * DI + d;
    float*       yp = g_y  + (size_t)s * LSEQ * DI + d;

    if (fast) {
        // A[n] == -(n+1): exp(dt*A[n]) = r^(n+1), r = exp(-dt). 1 MUFU/step.
        for (int t = 0; t < LSEQ; t++) {
            float acc = bd;
            #pragma unroll
            for (int i = 0; i < DTR; i++) acc = fmaf(Rs[t][i], w[i], acc);
            float dt = softplusf(acc);
            float xc = xp[t * DI];
            float dtx = dt * xc;
            float r = __expf(-dt);
            float y = 0.f, p = 1.f;
            #pragma unroll
            for (int n = 0; n < DST; n++) {
                p *= r;
                h[n] = fmaf(p, h[n], dtx * Bs[t][n]);
                y = fmaf(h[n], Cs[t][n], y);
            }
            yp[t * DI] = fmaf(xc, Dd, y);
        }
    } else {
        for (int t = 0; t < LSEQ; t++) {
            float acc = bd;
            #pragma unroll
            for (int i = 0; i < DTR; i++) acc = fmaf(Rs[t][i], w[i], acc);
            float dt = softplusf(acc);
            float xc = xp[t * DI];
            float dtx = dt * xc;
            float y = 0.f;
            #pragma unroll
            for (int n = 0; n < DST; n++) {
                float dA = __expf(dt * A[n]);
                h[n] = fmaf(dA, h[n], dtx * Bs[t][n]);
                y = fmaf(h[n], Cs[t][n], y);
            }
            yp[t * DI] = fmaf(xc, Dd, y);
        }
    }
}

// ---------------- gate: yb16 = y * silu(z), split to bf16 hi/lo (y includes xc*D) ----------------
__global__ void k_gate(int dummy) {
    size_t i = (size_t)blockIdx.x * 256 + threadIdx.x;
    int d = (int)(i & (DI - 1));
    size_t m = i >> 9;
    float z = g_xz[m * NXZ + DI + d];
    float v = g_y[i] * siluf(z);
    __nv_bfloat16 h = __float2bfloat16(v);
    g_yh[i] = h;
    g_yl[i] = __float2bfloat16(v - __bfloat162float(h));
}

// ---------------- scatter g_tmp -> out(b,c,h,w) ----------------
__global__ void k_scatter(float* __restrict__ out, int dir, int accum) {
    __shared__ float tile[32][33];
    int rt = blockIdx.x, ct = blockIdx.y, b = blockIdx.z;
    int tx = threadIdx.x, ty = threadIdx.y;
    int c0 = ct * 32;
    if (dir == 0) {
        int rem0 = rt * 32;
        #pragma unroll
        for (int i = 0; i < 4; i++) {
            int rem = rem0 + ty + i * 8;
            tile[ty + i * 8][tx] = g_tmp[(size_t)(b * 4096 + rem) * CDIM + c0 + tx];
        }
        __syncthreads();
        #pragma unroll
        for (int i = 0; i < 4; i++) {
            int c = c0 + ty + i * 8;
            size_t o = (size_t)(b * 256 + c) * 4096 + rem0 + tx;
            float v = tile[tx][ty + i * 8];
            if (accum) out[o] += v; else out[o] = v;
        }
    } else {
        int h = rt >> 1, w0 = (rt & 1) * 32;
        #pragma unroll
        for (int i = 0; i < 4; i++) {
            int w = w0 + ty + i * 8;
            tile[ty + i * 8][tx] = g_tmp[(size_t)(b * 4096 + w * 64 + h) * CDIM + c0 + tx];
        }
        __syncthreads();
        #pragma unroll
        for (int i = 0; i < 4; i++) {
            int c = c0 + ty + i * 8;
            size_t o = (size_t)(b * 256 + c) * 4096 + h * 64 + w0 + tx;
            float v = tile[tx][ty + i * 8];
            if (accum) out[o] += v; else out[o] = v;
        }
    }
}

// ---------------- launch ----------------
extern "C" void kernel_launch(void* const* d_in, const int* in_sizes, int n_in,
                              void* d_out, int out_size) {
    const float* x = (const float*)d_in[0];
    float* out = (float*)d_out;

    cudaError_t e = cudaFuncSetAttribute(k_mma_gemm32,
        cudaFuncAttributeMaxDynamicSharedMemorySize, 2 * STG32 * 2);
    bool use32 = (e == cudaSuccess);
    cudaGetLastError();

    k_transpose_hw<<<dim3(2, 2, 2048), dim3(32, 8)>>>(x);

    for (int dir = 0; dir < 2; dir++) {
        const float* Win  = (const float*)d_in[1 + dir * 9 + 0];
        const float* cw   = (const float*)d_in[1 + dir * 9 + 1];
        const float* cb   = (const float*)d_in[1 + dir * 9 + 2];
        const float* Wx   = (const float*)d_in[1 + dir * 9 + 3];
        const float* Wdt  = (const float*)d_in[1 + dir * 9 + 4];
        const float* bdt  = (const float*)d_in[1 + dir * 9 + 5];
        const float* Alog = (const float*)d_in[1 + dir * 9 + 6];
        const float* Dp   = (const float*)d_in[1 + dir * 9 + 7];
        const float* Wout = (const float*)d_in[1 + dir * 9 + 8];

        k_convA<<<dim3(128, 8, 8), dim3(32, 8)>>>(x, dir);
        k_convW<<<dim3(1024 / 32, 256 / 32), dim3(32, 8)>>>(Win, 256, 1024, 0);
        if (use32) k_mma_gemm32<<<dim3(8, 256), 256, 2 * STG32 * 2>>>(0);
        else       k_mma_gemm16<<<dim3(8, 256), 256>>>(0);
        k_conv_silu<<<dim3(NSEQ, 4), 128>>>(cw, cb);
        k_xproj<<<MDIM / 64, 256>>>(Wx);
        k_scan<<<NSEQ, 512>>>(Alog, Wdt, bdt, Dp);
        k_gate<<<(MDIM * DI) / 256, 256>>>(0);
        k_convW<<<dim3(256 / 32, 512 / 32), dim3(32, 8)>>>(Wout, 512, 256, 1);
        if (use32) k_mma_gemm32<<<dim3(2, 256), 256, 2 * STG32 * 2>>>(1);
        else       k_mma_gemm16<<<dim3(2, 256), 256>>>(1);
        k_scatter<<<dim3(128, 8, 8), dim3(32, 8)>>>(out, dir, dir);
    }
}

// round 11
// speedup vs baseline: 1.0899x; 1.0899x over previous
#include <cuda_runtime.h>
#include <cuda_bf16.h>
#include <cstdint>
#include <math.h>

// ---------------- problem constants ----------------
#define NSEQ   512
#define LSEQ   64
#define MDIM   (NSEQ*LSEQ)  // 32768
#define CDIM   256
#define DI     512
#define NXZ    1024
#define DST    16
#define DTR    16
#define NXP    48

// ---------------- scratch (device symbols: referenced ONLY inside device code) ----------------
__device__ float g_z  [MDIM * DI];      // 67 MB : z half of in-proj
__device__ float g_xraw[MDIM * DI];     // 67 MB : pre-conv x (fallback path only)
__device__ float g_xc [MDIM * DI];      // 67 MB : conv+silu output
__device__ float g_dbc[MDIM * NXP];     // 6.3 MB
__device__ float g_y  [MDIM * DI];      // 67 MB (scan out, includes +xc*D)
__device__ float g_tmp[MDIM * CDIM];    // 33.5 MB
__device__ float g_xT [8 * 256 * 64 * 64];
__device__ __nv_bfloat16 g_ah [MDIM * 256];
__device__ __nv_bfloat16 g_al [MDIM * 256];
__device__ __nv_bfloat16 g_yh [MDIM * DI];
__device__ __nv_bfloat16 g_yl [MDIM * DI];
__device__ __nv_bfloat16 g_wtih[1024 * 256];
__device__ __nv_bfloat16 g_wtil[1024 * 256];
__device__ __nv_bfloat16 g_wtoh[256 * 512];
__device__ __nv_bfloat16 g_wtol[256 * 512];

__device__ __forceinline__ float siluf(float v)    { return v / (1.f + __expf(-v)); }
__device__ __forceinline__ float softplusf(float v){ return (v > 20.f) ? v : log1pf(expf(v)); }

// ---------------- mma.sync / cp.async helpers ----------------
__device__ __forceinline__ void mma16816(float* c, const uint32_t* a, const uint32_t* b) {
    asm volatile(
        "mma.sync.aligned.m16n8k16.row.col.f32.bf16.bf16.f32 "
        "{%0,%1,%2,%3}, {%4,%5,%6,%7}, {%8,%9}, {%0,%1,%2,%3};\n"
        : "+f"(c[0]), "+f"(c[1]), "+f"(c[2]), "+f"(c[3])
        : "r"(a[0]), "r"(a[1]), "r"(a[2]), "r"(a[3]), "r"(b[0]), "r"(b[1]));
}
__device__ __forceinline__ void cp16(uint32_t saddr, const void* g) {
    asm volatile("cp.async.cg.shared.global [%0], [%1], 16;" :: "r"(saddr), "l"(g));
}
#define CP_COMMIT() asm volatile("cp.async.commit_group;" ::: "memory")
#define CP_WAIT(n)  asm volatile("cp.async.wait_group %0;" :: "n"(n) : "memory")

// ---------------- transpose x(b,c,h,w) -> xT(b,c,w,h) ----------------
__global__ void k_transpose_hw(const float* __restrict__ x) {
    __shared__ float tile[32][33];
    int bc = blockIdx.z, ht = blockIdx.y, wt = blockIdx.x;
    const float* src = x    + (size_t)bc * 4096;
    float*       dst = g_xT + (size_t)bc * 4096;
    int tx = threadIdx.x, ty = threadIdx.y;
    #pragma unroll
    for (int i = 0; i < 4; i++) {
        int h = ht * 32 + ty + i * 8;
        tile[ty + i * 8][tx] = src[h * 64 + wt * 32 + tx];
    }
    __syncthreads();
    #pragma unroll
    for (int i = 0; i < 4; i++) {
        int w = wt * 32 + ty + i * 8;
        dst[w * 64 + ht * 32 + tx] = tile[tx][ty + i * 8];
    }
}

// ---------------- convert A: src[(b*256+k)*4096+rem] -> bf16 hi/lo [m][k] ----------------
__global__ void k_convA(const float* __restrict__ xin, int useT) {
    __shared__ float t[32][33];
    const float* src = useT ? g_xT : xin;
    int b = blockIdx.z, kt = blockIdx.y, rt = blockIdx.x;
    int tx = threadIdx.x, ty = threadIdx.y;
    #pragma unroll
    for (int i = 0; i < 4; i++) {
        int k = kt * 32 + ty + i * 8;
        t[ty + i * 8][tx] = src[(size_t)(b * 256 + k) * 4096 + rt * 32 + tx];
    }
    __syncthreads();
    #pragma unroll
    for (int i = 0; i < 4; i++) {
        int rem = rt * 32 + ty + i * 8;
        size_t m = (size_t)b * 4096 + rem;
        float v = t[tx][ty + i * 8];
        __nv_bfloat16 h = __float2bfloat16(v);
        g_ah[m * 256 + kt * 32 + tx] = h;
        g_al[m * 256 + kt * 32 + tx] = __float2bfloat16(v - __bfloat162float(h));
    }
}

// ---------------- convert+transpose weights: W[R,C] fp32 -> T[C,R] bf16 hi/lo ----------------
__global__ void k_convW(const float* __restrict__ W, int R, int C, int which) {
    __shared__ float t[32][33];
    __nv_bfloat16* Th = which ? g_wtoh : g_wtih;
    __nv_bfloat16* Tl = which ? g_wtol : g_wtil;
    int r0 = blockIdx.y * 32, c0 = blockIdx.x * 32;
    int tx = threadIdx.x, ty = threadIdx.y;
    #pragma unroll
    for (int i = 0; i < 4; i++)
        t[ty + i * 8][tx] = W[(size_t)(r0 + ty + i * 8) * C + c0 + tx];
    __syncthreads();
    #pragma unroll
    for (int i = 0; i < 4; i++) {
        float v = t[tx][ty + i * 8];
        int oc = c0 + ty + i * 8;
        __nv_bfloat16 h = __float2bfloat16(v);
        Th[(size_t)oc * R + r0 + tx] = h;
        Tl[(size_t)oc * R + r0 + tx] = __float2bfloat16(v - __bfloat162float(h));
    }
}

// ---------------- shared GEMM config ----------------
__device__ __forceinline__ void gemm_cfg(int mode, const __nv_bfloat16*& Ah,
    const __nv_bfloat16*& Al, const __nv_bfloat16*& Bh, const __nv_bfloat16*& Bl,
    int& K)
{
    if (mode == 0) { Ah = g_ah; Al = g_al; Bh = g_wtih; Bl = g_wtil; K = 256; }
    else           { Ah = g_yh; Al = g_yl; Bh = g_wtoh; Bl = g_wtol; K = 512; }
}

__device__ __forceinline__ void gemm_epilogue(float acc[4][4][4], float* Cout, int ldc,
                                              int m0, int n0, int wr, int wc, int g, int tg)
{
    #pragma unroll
    for (int mt = 0; mt < 4; mt++)
        #pragma unroll
        for (int nt = 0; nt < 4; nt++) {
            int row = m0 + wr * 64 + mt * 16 + g;
            int col = n0 + wc * 32 + nt * 8 + tg * 2;
            *(float2*)&Cout[(size_t)row * ldc + col] =
                make_float2(acc[mt][nt][0], acc[mt][nt][1]);
            *(float2*)&Cout[(size_t)(row + 8) * ldc + col] =
                make_float2(acc[mt][nt][2], acc[mt][nt][3]);
        }
}

// ---------------- HMMA bf16x3 GEMM, BK=32, cp.async 2-stage, DYNAMIC smem ----------------
// mode 0: xz GEMM. Blocks bx<4 compute the x half and FUSE conv+silu -> g_xc.
//         Blocks bx>=4 compute the z half -> g_z (col n0-512, ld DI).
//         (m-tile of 128 rows = exactly 2 complete sequences; conv is block-local.)
// mode 1: out GEMM -> g_tmp.
#define SSTR32 40
#define TILE32 (128 * SSTR32)
#define STG32  (4 * TILE32)
#define SSTG   132
__global__ void __launch_bounds__(256, 2) k_mma_gemm32(int mode,
        const float* __restrict__ cw, const float* __restrict__ cb) {
    extern __shared__ __nv_bfloat16 dsm[];

    const __nv_bfloat16 *Ah, *Al, *Bh, *Bl;
    int K;
    gemm_cfg(mode, Ah, Al, Bh, Bl, K);

    int tid = threadIdx.x, warp = tid >> 5, lane = tid & 31;
    int wr = warp >> 2, wc = warp & 3;
    int g = lane >> 2, tg = lane & 3;
    int m0 = blockIdx.y * 128, n0 = blockIdx.x * 128;

    const __nv_bfloat16* base0 = Ah + (size_t)m0 * K;
    const __nv_bfloat16* base1 = Al + (size_t)m0 * K;
    const __nv_bfloat16* base2 = Bh + (size_t)n0 * K;
    const __nv_bfloat16* base3 = Bl + (size_t)n0 * K;

    uint32_t sbase = (uint32_t)__cvta_generic_to_shared(dsm);
    float acc[4][4][4];
    #pragma unroll
    for (int i = 0; i < 4; i++)
        #pragma unroll
        for (int j = 0; j < 4; j++)
            #pragma unroll
            for (int q = 0; q < 4; q++) acc[i][j][q] = 0.f;

    #pragma unroll
    for (int i = 0; i < 2; i++) {
        int idx = tid + i * 256;
        int r = idx >> 2, q = idx & 3;
        size_t go = (size_t)r * K + q * 8;
        uint32_t so = sbase + (uint32_t)(r * SSTR32 + q * 8) * 2;
        cp16(so + 0 * TILE32 * 2, base0 + go);
        cp16(so + 1 * TILE32 * 2, base1 + go);
        cp16(so + 2 * TILE32 * 2, base2 + go);
        cp16(so + 3 * TILE32 * 2, base3 + go);
    }
    CP_COMMIT();

    const int T = K >> 5;
    for (int it = 0; it < T; it++) {
        if (it + 1 < T) {
            int k0n = (it + 1) << 5;
            uint32_t sb = sbase + ((it + 1) & 1) * STG32 * 2;
            #pragma unroll
            for (int i = 0; i < 2; i++) {
                int idx = tid + i * 256;
                int r = idx >> 2, q = idx & 3;
                size_t go = (size_t)r * K + q * 8 + k0n;
                uint32_t so = sb + (uint32_t)(r * SSTR32 + q * 8) * 2;
                cp16(so + 0 * TILE32 * 2, base0 + go);
                cp16(so + 1 * TILE32 * 2, base1 + go);
                cp16(so + 2 * TILE32 * 2, base2 + go);
                cp16(so + 3 * TILE32 * 2, base3 + go);
            }
            CP_COMMIT();
            CP_WAIT(1);
        } else {
            CP_WAIT(0);
        }
        __syncthreads();

        const __nv_bfloat16* s0  = dsm + (it & 1) * STG32;
        const __nv_bfloat16* sAh = s0;
        const __nv_bfloat16* sAl = s0 + TILE32;
        const __nv_bfloat16* sBh = s0 + 2 * TILE32;
        const __nv_bfloat16* sBl = s0 + 3 * TILE32;

        #pragma unroll
        for (int ks = 0; ks < 2; ks++) {
            int kb = ks * 16 + tg * 2;
            uint32_t a_hi[4][4], a_lo[4][4], b_hi[4][2], b_lo[4][2];
            #pragma unroll
            for (int mt = 0; mt < 4; mt++) {
                int row = wr * 64 + mt * 16 + g;
                a_hi[mt][0] = *(const uint32_t*)&sAh[row * SSTR32 + kb];
                a_hi[mt][1] = *(const uint32_t*)&sAh[(row + 8) * SSTR32 + kb];
                a_hi[mt][2] = *(const uint32_t*)&sAh[row * SSTR32 + kb + 8];
                a_hi[mt][3] = *(const uint32_t*)&sAh[(row + 8) * SSTR32 + kb + 8];
                a_lo[mt][0] = *(const uint32_t*)&sAl[row * SSTR32 + kb];
                a_lo[mt][1] = *(const uint32_t*)&sAl[(row + 8) * SSTR32 + kb];
                a_lo[mt][2] = *(const uint32_t*)&sAl[row * SSTR32 + kb + 8];
                a_lo[mt][3] = *(const uint32_t*)&sAl[(row + 8) * SSTR32 + kb + 8];
            }
            #pragma unroll
            for (int nt = 0; nt < 4; nt++) {
                int rn = wc * 32 + nt * 8 + g;
                b_hi[nt][0] = *(const uint32_t*)&sBh[rn * SSTR32 + kb];
                b_hi[nt][1] = *(const uint32_t*)&sBh[rn * SSTR32 + kb + 8];
                b_lo[nt][0] = *(const uint32_t*)&sBl[rn * SSTR32 + kb];
                b_lo[nt][1] = *(const uint32_t*)&sBl[rn * SSTR32 + kb + 8];
            }
            #pragma unroll
            for (int mt = 0; mt < 4; mt++)
                #pragma unroll
                for (int nt = 0; nt < 4; nt++) {
                    mma16816(acc[mt][nt], a_hi[mt], b_hi[nt]);
                    mma16816(acc[mt][nt], a_hi[mt], b_lo[nt]);
                    mma16816(acc[mt][nt], a_lo[mt], b_hi[nt]);
                }
        }
        __syncthreads();
    }

    if (mode == 0) {
        if (blockIdx.x < 4) {
            // x half: stage tile in smem, fused causal conv(4)+bias+silu -> g_xc
            float* stage = (float*)dsm;   // 128 x SSTG fp32 = 67584 B <= 81920 B
            #pragma unroll
            for (int mt = 0; mt < 4; mt++)
                #pragma unroll
                for (int nt = 0; nt < 4; nt++) {
                    int row = wr * 64 + mt * 16 + g;
                    int col = wc * 32 + nt * 8 + tg * 2;
                    *(float2*)&stage[row * SSTG + col] =
                        make_float2(acc[mt][nt][0], acc[mt][nt][1]);
                    *(float2*)&stage[(row + 8) * SSTG + col] =
                        make_float2(acc[mt][nt][2], acc[mt][nt][3]);
                }
            __syncthreads();
            int dl = tid & 127;        // local channel
            int sh = tid >> 7;         // sequence half (0/1)
            int dg = n0 + dl;          // global channel
            float w0 = cw[dg * 4 + 0], w1 = cw[dg * 4 + 1];
            float w2 = cw[dg * 4 + 2], w3 = cw[dg * 4 + 3];
            float bias = cb[dg];
            float x0 = 0.f, x1 = 0.f, x2 = 0.f;
            const float* sp = stage + (sh * 64) * SSTG + dl;
            float* op = g_xc + (size_t)(m0 + sh * 64) * DI + dg;
            #pragma unroll 4
            for (int t = 0; t < LSEQ; t++) {
                float x3 = sp[t * SSTG];
                float a = fmaf(w3, x3, fmaf(w2, x2, fmaf(w1, x1, fmaf(w0, x0, bias))));
                op[t * DI] = siluf(a);
                x0 = x1; x1 = x2; x2 = x3;
            }
        } else {
            gemm_epilogue(acc, g_z, DI, m0, n0 - 512, wr, wc, g, tg);
        }
    } else {
        gemm_epilogue(acc, g_tmp, CDIM, m0, n0, wr, wc, g, tg);
    }
}

// ---------------- fallback: BK=16, static smem (no conv fusion) ----------------
#define SSTR 24
#define TILE_E (128 * SSTR)
#define STAGE_E (4 * TILE_E)
__global__ void __launch_bounds__(256, 2) k_mma_gemm16(int mode) {
    __shared__ __align__(16) __nv_bfloat16 smem[2 * STAGE_E];

    const __nv_bfloat16 *Ah, *Al, *Bh, *Bl;
    int K;
    gemm_cfg(mode, Ah, Al, Bh, Bl, K);

    int tid = threadIdx.x, warp = tid >> 5, lane = tid & 31;
    int wr = warp >> 2, wc = warp & 3;
    int g = lane >> 2, tg = lane & 3;
    int m0 = blockIdx.y * 128, n0 = blockIdx.x * 128;

    const __nv_bfloat16* base0 = Ah + (size_t)m0 * K;
    const __nv_bfloat16* base1 = Al + (size_t)m0 * K;
    const __nv_bfloat16* base2 = Bh + (size_t)n0 * K;
    const __nv_bfloat16* base3 = Bl + (size_t)n0 * K;

    uint32_t sbase = (uint32_t)__cvta_generic_to_shared(smem);
    int lr = tid >> 1, lq = tid & 1;
    size_t goff = (size_t)lr * K + lq * 8;
    uint32_t soff = (uint32_t)(lr * SSTR + lq * 8) * 2;

    float acc[4][4][4];
    #pragma unroll
    for (int i = 0; i < 4; i++)
        #pragma unroll
        for (int j = 0; j < 4; j++)
            #pragma unroll
            for (int q = 0; q < 4; q++) acc[i][j][q] = 0.f;

    {
        uint32_t sb = sbase + soff;
        cp16(sb + 0 * TILE_E * 2, base0 + goff);
        cp16(sb + 1 * TILE_E * 2, base1 + goff);
        cp16(sb + 2 * TILE_E * 2, base2 + goff);
        cp16(sb + 3 * TILE_E * 2, base3 + goff);
        CP_COMMIT();
    }

    const int T = K >> 4;
    for (int it = 0; it < T; it++) {
        if (it + 1 < T) {
            int k0n = (it + 1) << 4;
            uint32_t sb = sbase + ((it + 1) & 1) * STAGE_E * 2 + soff;
            cp16(sb + 0 * TILE_E * 2, base0 + goff + k0n);
            cp16(sb + 1 * TILE_E * 2, base1 + goff + k0n);
            cp16(sb + 2 * TILE_E * 2, base2 + goff + k0n);
            cp16(sb + 3 * TILE_E * 2, base3 + goff + k0n);
            CP_COMMIT();
            CP_WAIT(1);
        } else {
            CP_WAIT(0);
        }
        __syncthreads();

        const __nv_bfloat16* s0 = smem + (it & 1) * STAGE_E;
        const __nv_bfloat16* sAh = s0;
        const __nv_bfloat16* sAl = s0 + TILE_E;
        const __nv_bfloat16* sBh = s0 + 2 * TILE_E;
        const __nv_bfloat16* sBl = s0 + 3 * TILE_E;
        int kb = tg * 2;

        uint32_t a_hi[4][4], a_lo[4][4], b_hi[4][2], b_lo[4][2];
        #pragma unroll
        for (int mt = 0; mt < 4; mt++) {
            int row = wr * 64 + mt * 16 + g;
            a_hi[mt][0] = *(const uint32_t*)&sAh[row * SSTR + kb];
            a_hi[mt][1] = *(const uint32_t*)&sAh[(row + 8) * SSTR + kb];
            a_hi[mt][2] = *(const uint32_t*)&sAh[row * SSTR + kb + 8];
            a_hi[mt][3] = *(const uint32_t*)&sAh[(row + 8) * SSTR + kb + 8];
            a_lo[mt][0] = *(const uint32_t*)&sAl[row * SSTR + kb];
            a_lo[mt][1] = *(const uint32_t*)&sAl[(row + 8) * SSTR + kb];
            a_lo[mt][2] = *(const uint32_t*)&sAl[row * SSTR + kb + 8];
            a_lo[mt][3] = *(const uint32_t*)&sAl[(row + 8) * SSTR + kb + 8];
        }
        #pragma unroll
        for (int nt = 0; nt < 4; nt++) {
            int rn = wc * 32 + nt * 8 + g;
            b_hi[nt][0] = *(const uint32_t*)&sBh[rn * SSTR + kb];
            b_hi[nt][1] = *(const uint32_t*)&sBh[rn * SSTR + kb + 8];
            b_lo[nt][0] = *(const uint32_t*)&sBl[rn * SSTR + kb];
            b_lo[nt][1] = *(const uint32_t*)&sBl[rn * SSTR + kb + 8];
        }
        #pragma unroll
        for (int mt = 0; mt < 4; mt++)
            #pragma unroll
            for (int nt = 0; nt < 4; nt++) {
                mma16816(acc[mt][nt], a_hi[mt], b_hi[nt]);
                mma16816(acc[mt][nt], a_hi[mt], b_lo[nt]);
                mma16816(acc[mt][nt], a_lo[mt], b_hi[nt]);
            }
        __syncthreads();
    }
    if (mode == 0) {
        if (blockIdx.x < 4) gemm_epilogue(acc, g_xraw, DI, m0, n0, wr, wc, g, tg);
        else                gemm_epilogue(acc, g_z, DI, m0, n0 - 512, wr, wc, g, tg);
    } else {
        gemm_epilogue(acc, g_tmp, CDIM, m0, n0, wr, wc, g, tg);
    }
}

// ---------------- depthwise conv(4, causal) + bias + silu (FALLBACK path only) ----------------
__global__ void k_conv_silu(const float* __restrict__ cw, const float* __restrict__ cb) {
    int s = blockIdx.x;
    int d = blockIdx.y * 128 + threadIdx.x;
    float w0 = cw[d * 4 + 0], w1 = cw[d * 4 + 1], w2 = cw[d * 4 + 2], w3 = cw[d * 4 + 3];
    float bias = cb[d];
    float x0 = 0.f, x1 = 0.f, x2 = 0.f;
    const float* xp = g_xraw + (size_t)s * LSEQ * DI + d;
    float*       op = g_xc   + (size_t)s * LSEQ * DI + d;
    #pragma unroll 4
    for (int t = 0; t < LSEQ; t++) {
        float x3 = xp[t * DI];
        float a = fmaf(w3, x3, fmaf(w2, x2, fmaf(w1, x1, fmaf(w0, x0, bias))));
        op[t * DI] = siluf(a);
        x0 = x1; x1 = x2; x2 = x3;
    }
}

// ---------------- x-proj GEMM: g_dbc[m, 0:48] = g_xc[m,:] @ W_xproj ----------------
__global__ void __launch_bounds__(256) k_xproj(const float* __restrict__ Wx) {
    __shared__ __align__(16) float As[32][68];
    __shared__ float Bs[32][48];
    int m0 = blockIdx.x * 64;
    int tid = threadIdx.x;
    int rg = tid & 15;
    int cg = tid >> 4;
    float acc[4][3];
    #pragma unroll
    for (int i = 0; i < 4; i++)
        #pragma unroll
        for (int j = 0; j < 3; j++) acc[i][j] = 0.f;

    for (int k0 = 0; k0 < DI; k0 += 32) {
        #pragma unroll
        for (int i = 0; i < 2; i++) {
            int idx = tid + i * 256;
            int r = idx >> 3, kc = (idx & 7) * 4;
            float4 v = *(const float4*)&g_xc[(size_t)(m0 + r) * DI + k0 + kc];
            As[kc + 0][r] = v.x; As[kc + 1][r] = v.y;
            As[kc + 2][r] = v.z; As[kc + 3][r] = v.w;
        }
        #pragma unroll
        for (int i = 0; i < 6; i++) {
            int idx = tid + i * 256;
            int k = idx / 48, n = idx % 48;
            Bs[k][n] = Wx[(k0 + k) * NXP + n];
        }
        __syncthreads();
        #pragma unroll
        for (int k = 0; k < 32; k++) {
            float4 a = *(const float4*)&As[k][rg * 4];
            float b0 = Bs[k][cg * 3 + 0];
            float b1 = Bs[k][cg * 3 + 1];
            float b2 = Bs[k][cg * 3 + 2];
            acc[0][0] = fmaf(a.x, b0, acc[0][0]);
            acc[0][1] = fmaf(a.x, b1, acc[0][1]);
            acc[0][2] = fmaf(a.x, b2, acc[0][2]);
            acc[1][0] = fmaf(a.y, b0, acc[1][0]);
            acc[1][1] = fmaf(a.y, b1, acc[1][1]);
            acc[1][2] = fmaf(a.y, b2, acc[1][2]);
            acc[2][0] = fmaf(a.z, b0, acc[2][0]);
            acc[2][1] = fmaf(a.z, b1, acc[2][1]);
            acc[2][2] = fmaf(a.z, b2, acc[2][2]);
            acc[3][0] = fmaf(a.w, b0, acc[3][0]);
            acc[3][1] = fmaf(a.w, b1, acc[3][1]);
            acc[3][2] = fmaf(a.w, b2, acc[3][2]);
        }
        __syncthreads();
    }
    #pragma unroll
    for (int i = 0; i < 4; i++)
        #pragma unroll
        for (int j = 0; j < 3; j++)
            g_dbc[(size_t)(m0 + rg * 4 + i) * NXP + cg * 3 + j] = acc[i][j];
}

// ---------------- selective scan (dt-proj fused; exp-recurrence; writes y+xc*D) ----------------
__global__ void __launch_bounds__(512) k_scan(const float* __restrict__ Alog,
                                              const float* __restrict__ Wdt,
                                              const float* __restrict__ bdt,
                                              const float* __restrict__ Dp) {
    __shared__ float Rs[LSEQ][DTR];
    __shared__ float Bs[LSEQ][DST];
    __shared__ float Cs[LSEQ][DST];
    int s = blockIdx.x;
    int d = threadIdx.x;
    for (int i = threadIdx.x; i < LSEQ * NXP; i += 512) {
        int t = i / NXP, j = i % NXP;
        float v = g_dbc[(size_t)(s * LSEQ + t) * NXP + j];
        if (j < DTR) Rs[t][j] = v;
        else if (j < DTR + DST) Bs[t][j - DTR] = v;
        else Cs[t][j - DTR - DST] = v;
    }
    __syncthreads();
    float A[DST], h[DST], w[DTR];
    bool fast = true;
    #pragma unroll
    for (int n = 0; n < DST; n++) {
        A[n] = -expf(Alog[d * DST + n]);
        h[n] = 0.f;
        fast = fast && (fabsf(A[n] + (float)(n + 1)) <= 1e-3f * (float)(n + 1));
    }
    #pragma unroll
    for (int i = 0; i < DTR; i++) w[i] = Wdt[i * DI + d];
    float bd = bdt[d];
    float Dd = Dp[d];
    const float* xp = g_xc + (size_t)s * LSEQ * DI + d;
    float*       yp = g_y  + (size_t)s * LSEQ * DI + d;

    if (fast) {
        for (int t = 0; t < LSEQ; t++) {
            float acc = bd;
            #pragma unroll
            for (int i = 0; i < DTR; i++) acc = fmaf(Rs[t][i], w[i], acc);
            float dt = softplusf(acc);
            float xc = xp[t * DI];
            float dtx = dt * xc;
            float r = __expf(-dt);
            float y = 0.f, p = 1.f;
            #pragma unroll
            for (int n = 0; n < DST; n++) {
                p *= r;
                h[n] = fmaf(p, h[n], dtx * Bs[t][n]);
                y = fmaf(h[n], Cs[t][n], y);
            }
            yp[t * DI] = fmaf(xc, Dd, y);
        }
    } else {
        for (int t = 0; t < LSEQ; t++) {
            float acc = bd;
            #pragma unroll
            for (int i = 0; i < DTR; i++) acc = fmaf(Rs[t][i], w[i], acc);
            float dt = softplusf(acc);
            float xc = xp[t * DI];
            float dtx = dt * xc;
            float y = 0.f;
            #pragma unroll
            for (int n = 0; n < DST; n++) {
                float dA = __expf(dt * A[n]);
                h[n] = fmaf(dA, h[n], dtx * Bs[t][n]);
                y = fmaf(h[n], Cs[t][n], y);
            }
            yp[t * DI] = fmaf(xc, Dd, y);
        }
    }
}

// ---------------- gate: yb16 = y * silu(z), float4-vectorized ----------------
__global__ void k_gate(int dummy) {
    size_t i = ((size_t)blockIdx.x * 256 + threadIdx.x) * 4;
    float4 y = *(const float4*)&g_y[i];
    float4 z = *(const float4*)&g_z[i];
    float v0 = y.x * siluf(z.x);
    float v1 = y.y * siluf(z.y);
    float v2 = y.z * siluf(z.z);
    float v3 = y.w * siluf(z.w);
    __nv_bfloat16 h0 = __float2bfloat16(v0), h1 = __float2bfloat16(v1);
    __nv_bfloat16 h2 = __float2bfloat16(v2), h3 = __float2bfloat16(v3);
    __nv_bfloat16 hv[4] = {h0, h1, h2, h3};
    __nv_bfloat16 lv[4] = {
        __float2bfloat16(v0 - __bfloat162float(h0)),
        __float2bfloat16(v1 - __bfloat162float(h1)),
        __float2bfloat16(v2 - __bfloat162float(h2)),
        __float2bfloat16(v3 - __bfloat162float(h3))};
    *(uint2*)&g_yh[i] = *(const uint2*)hv;
    *(uint2*)&g_yl[i] = *(const uint2*)lv;
}

// ---------------- scatter g_tmp -> out(b,c,h,w) ----------------
__global__ void k_scatter(float* __restrict__ out, int dir, int accum) {
    __shared__ float tile[32][33];
    int rt = blockIdx.x, ct = blockIdx.y, b = blockIdx.z;
    int tx = threadIdx.x, ty = threadIdx.y;
    int c0 = ct * 32;
    if (dir == 0) {
        int rem0 = rt * 32;
        #pragma unroll
        for (int i = 0; i < 4; i++) {
            int rem = rem0 + ty + i * 8;
            tile[ty + i * 8][tx] = g_tmp[(size_t)(b * 4096 + rem) * CDIM + c0 + tx];
        }
        __syncthreads();
        #pragma unroll
        for (int i = 0; i < 4; i++) {
            int c = c0 + ty + i * 8;
            size_t o = (size_t)(b * 256 + c) * 4096 + rem0 + tx;
            float v = tile[tx][ty + i * 8];
            if (accum) out[o] += v; else out[o] = v;
        }
    } else {
        int h = rt >> 1, w0 = (rt & 1) * 32;
        #pragma unroll
        for (int i = 0; i < 4; i++) {
            int w = w0 + ty + i * 8;
            tile[ty + i * 8][tx] = g_tmp[(size_t)(b * 4096 + w * 64 + h) * CDIM + c0 + tx];
        }
        __syncthreads();
        #pragma unroll
        for (int i = 0; i < 4; i++) {
            int c = c0 + ty + i * 8;
            size_t o = (size_t)(b * 256 + c) * 4096 + h * 64 + w0 + tx;
            float v = tile[tx][ty + i * 8];
            if (accum) out[o] += v; else out[o] = v;
        }
    }
}

// ---------------- launch ----------------
extern "C" void kernel_launch(void* const* d_in, const int* in_sizes, int n_in,
                              void* d_out, int out_size) {
    const float* x = (const float*)d_in[0];
    float* out = (float*)d_out;

    cudaError_t e = cudaFuncSetAttribute(k_mma_gemm32,
        cudaFuncAttributeMaxDynamicSharedMemorySize, 2 * STG32 * 2);
    bool use32 = (e == cudaSuccess);
    cudaGetLastError();

    k_transpose_hw<<<dim3(2, 2, 2048), dim3(32, 8)>>>(x);

    for (int dir = 0; dir < 2; dir++) {
        const float* Win  = (const float*)d_in[1 + dir * 9 + 0];
        const float* cw   = (const float*)d_in[1 + dir * 9 + 1];
        const float* cb   = (const float*)d_in[1 + dir * 9 + 2];
        const float* Wx   = (const float*)d_in[1 + dir * 9 + 3];
        const float* Wdt  = (const float*)d_in[1 + dir * 9 + 4];
        const float* bdt  = (const float*)d_in[1 + dir * 9 + 5];
        const float* Alog = (const float*)d_in[1 + dir * 9 + 6];
        const float* Dp   = (const float*)d_in[1 + dir * 9 + 7];
        const float* Wout = (const float*)d_in[1 + dir * 9 + 8];

        k_convA<<<dim3(128, 8, 8), dim3(32, 8)>>>(x, dir);
        k_convW<<<dim3(1024 / 32, 256 / 32), dim3(32, 8)>>>(Win, 256, 1024, 0);
        if (use32) {
            k_mma_gemm32<<<dim3(8, 256), 256, 2 * STG32 * 2>>>(0, cw, cb);
        } else {
            k_mma_gemm16<<<dim3(8, 256), 256>>>(0);
            k_conv_silu<<<dim3(NSEQ, 4), 128>>>(cw, cb);
        }
        k_xproj<<<MDIM / 64, 256>>>(Wx);
        k_scan<<<NSEQ, 512>>>(Alog, Wdt, bdt, Dp);
        k_gate<<<(MDIM * DI) / 1024, 256>>>(0);
        k_convW<<<dim3(256 / 32, 512 / 32), dim3(32, 8)>>>(Wout, 512, 256, 1);
        if (use32) k_mma_gemm32<<<dim3(2, 256), 256, 2 * STG32 * 2>>>(1, nullptr, nullptr);
        else       k_mma_gemm16<<<dim3(2, 256), 256>>>(1);
        k_scatter<<<dim3(128, 8, 8), dim3(32, 8)>>>(out, dir, dir);
    }
}

// round 12
// speedup vs baseline: 1.1281x; 1.0351x over previous
#include <cuda_runtime.h>
#include <cuda_bf16.h>
#include <cstdint>
#include <math.h>

// ---------------- problem constants ----------------
#define NSEQ   512
#define LSEQ   64
#define MDIM   (NSEQ*LSEQ)  // 32768
#define CDIM   256
#define DI     512
#define NXZ    1024
#define DST    16
#define DTR    16
#define NXP    48

// ---------------- scratch (device symbols: referenced ONLY inside device code) ----------------
__device__ float g_z  [MDIM * DI];      // 67 MB : z half of in-proj
__device__ float g_xraw[MDIM * DI];     // 67 MB : pre-conv x (fallback path only)
__device__ float g_xc [MDIM * DI];      // 67 MB : conv+silu output
__device__ float g_dbc[MDIM * NXP];     // 6.3 MB
__device__ float g_y  [MDIM * DI];      // 67 MB (scan out, includes +xc*D)
__device__ float g_tmp[MDIM * CDIM];    // 33.5 MB
__device__ float g_xT [8 * 256 * 64 * 64];
__device__ __nv_bfloat16 g_ah [MDIM * 256];
__device__ __nv_bfloat16 g_al [MDIM * 256];
__device__ __nv_bfloat16 g_yh [MDIM * DI];
__device__ __nv_bfloat16 g_yl [MDIM * DI];
__device__ __nv_bfloat16 g_wtih[1024 * 256];
__device__ __nv_bfloat16 g_wtil[1024 * 256];
__device__ __nv_bfloat16 g_wtoh[256 * 512];
__device__ __nv_bfloat16 g_wtol[256 * 512];

__device__ __forceinline__ float siluf(float v)    { return v / (1.f + __expf(-v)); }
__device__ __forceinline__ float softplusf(float v){ return (v > 20.f) ? v : log1pf(expf(v)); }

// ---------------- mma.sync / cp.async / ldmatrix helpers ----------------
__device__ __forceinline__ void mma16816(float* c, const uint32_t* a, const uint32_t* b) {
    asm volatile(
        "mma.sync.aligned.m16n8k16.row.col.f32.bf16.bf16.f32 "
        "{%0,%1,%2,%3}, {%4,%5,%6,%7}, {%8,%9}, {%0,%1,%2,%3};\n"
        : "+f"(c[0]), "+f"(c[1]), "+f"(c[2]), "+f"(c[3])
        : "r"(a[0]), "r"(a[1]), "r"(a[2]), "r"(a[3]), "r"(b[0]), "r"(b[1]));
}
__device__ __forceinline__ void cp16(uint32_t saddr, const void* g) {
    asm volatile("cp.async.cg.shared.global [%0], [%1], 16;" :: "r"(saddr), "l"(g));
}
__device__ __forceinline__ void ldsm4(uint32_t* r, uint32_t saddr) {
    asm volatile("ldmatrix.sync.aligned.m8n8.x4.shared.b16 {%0,%1,%2,%3}, [%4];"
        : "=r"(r[0]), "=r"(r[1]), "=r"(r[2]), "=r"(r[3]) : "r"(saddr));
}
#define CP_COMMIT() asm volatile("cp.async.commit_group;" ::: "memory")
#define CP_WAIT(n)  asm volatile("cp.async.wait_group %0;" :: "n"(n) : "memory")

// ---------------- transpose x(b,c,h,w) -> xT(b,c,w,h) ----------------
__global__ void k_transpose_hw(const float* __restrict__ x) {
    __shared__ float tile[32][33];
    int bc = blockIdx.z, ht = blockIdx.y, wt = blockIdx.x;
    const float* src = x    + (size_t)bc * 4096;
    float*       dst = g_xT + (size_t)bc * 4096;
    int tx = threadIdx.x, ty = threadIdx.y;
    #pragma unroll
    for (int i = 0; i < 4; i++) {
        int h = ht * 32 + ty + i * 8;
        tile[ty + i * 8][tx] = src[h * 64 + wt * 32 + tx];
    }
    __syncthreads();
    #pragma unroll
    for (int i = 0; i < 4; i++) {
        int w = wt * 32 + ty + i * 8;
        dst[w * 64 + ht * 32 + tx] = tile[tx][ty + i * 8];
    }
}

// ---------------- convert A: src[(b*256+k)*4096+rem] -> bf16 hi/lo [m][k] ----------------
__global__ void k_convA(const float* __restrict__ xin, int useT) {
    __shared__ float t[32][33];
    const float* src = useT ? g_xT : xin;
    int b = blockIdx.z, kt = blockIdx.y, rt = blockIdx.x;
    int tx = threadIdx.x, ty = threadIdx.y;
    #pragma unroll
    for (int i = 0; i < 4; i++) {
        int k = kt * 32 + ty + i * 8;
        t[ty + i * 8][tx] = src[(size_t)(b * 256 + k) * 4096 + rt * 32 + tx];
    }
    __syncthreads();
    #pragma unroll
    for (int i = 0; i < 4; i++) {
        int rem = rt * 32 + ty + i * 8;
        size_t m = (size_t)b * 4096 + rem;
        float v = t[tx][ty + i * 8];
        __nv_bfloat16 h = __float2bfloat16(v);
        g_ah[m * 256 + kt * 32 + tx] = h;
        g_al[m * 256 + kt * 32 + tx] = __float2bfloat16(v - __bfloat162float(h));
    }
}

// ---------------- convert+transpose weights: W[R,C] fp32 -> T[C,R] bf16 hi/lo ----------------
__global__ void k_convW(const float* __restrict__ W, int R, int C, int which) {
    __shared__ float t[32][33];
    __nv_bfloat16* Th = which ? g_wtoh : g_wtih;
    __nv_bfloat16* Tl = which ? g_wtol : g_wtil;
    int r0 = blockIdx.y * 32, c0 = blockIdx.x * 32;
    int tx = threadIdx.x, ty = threadIdx.y;
    #pragma unroll
    for (int i = 0; i < 4; i++)
        t[ty + i * 8][tx] = W[(size_t)(r0 + ty + i * 8) * C + c0 + tx];
    __syncthreads();
    #pragma unroll
    for (int i = 0; i < 4; i++) {
        float v = t[tx][ty + i * 8];
        int oc = c0 + ty + i * 8;
        __nv_bfloat16 h = __float2bfloat16(v);
        Th[(size_t)oc * R + r0 + tx] = h;
        Tl[(size_t)oc * R + r0 + tx] = __float2bfloat16(v - __bfloat162float(h));
    }
}

// ---------------- shared GEMM config ----------------
__device__ __forceinline__ void gemm_cfg(int mode, const __nv_bfloat16*& Ah,
    const __nv_bfloat16*& Al, const __nv_bfloat16*& Bh, const __nv_bfloat16*& Bl,
    int& K)
{
    if (mode == 0) { Ah = g_ah; Al = g_al; Bh = g_wtih; Bl = g_wtil; K = 256; }
    else           { Ah = g_yh; Al = g_yl; Bh = g_wtoh; Bl = g_wtol; K = 512; }
}

__device__ __forceinline__ void gemm_epilogue(float acc[4][4][4], float* Cout, int ldc,
                                              int m0, int n0, int wr, int wc, int g, int tg)
{
    #pragma unroll
    for (int mt = 0; mt < 4; mt++)
        #pragma unroll
        for (int nt = 0; nt < 4; nt++) {
            int row = m0 + wr * 64 + mt * 16 + g;
            int col = n0 + wc * 32 + nt * 8 + tg * 2;
            *(float2*)&Cout[(size_t)row * ldc + col] =
                make_float2(acc[mt][nt][0], acc[mt][nt][1]);
            *(float2*)&Cout[(size_t)(row + 8) * ldc + col] =
                make_float2(acc[mt][nt][2], acc[mt][nt][3]);
        }
}

// ---------------- HMMA bf16x3 GEMM, BK=32, cp.async 2-stage, ldmatrix fragments ----------------
// mode 0: xz GEMM. Blocks bx<4 compute the x half and FUSE conv+silu -> g_xc.
//         Blocks bx>=4 compute the z half -> g_z.
// mode 1: out GEMM -> g_tmp.
#define SSTR32 40
#define TILE32 (128 * SSTR32)
#define STG32  (4 * TILE32)
#define SSTG   132
__global__ void __launch_bounds__(256, 2) k_mma_gemm32(int mode,
        const float* __restrict__ cw, const float* __restrict__ cb) {
    extern __shared__ __nv_bfloat16 dsm[];

    const __nv_bfloat16 *Ah, *Al, *Bh, *Bl;
    int K;
    gemm_cfg(mode, Ah, Al, Bh, Bl, K);

    int tid = threadIdx.x, warp = tid >> 5, lane = tid & 31;
    int wr = warp >> 2, wc = warp & 3;
    int g = lane >> 2, tg = lane & 3;
    int m0 = blockIdx.y * 128, n0 = blockIdx.x * 128;

    const __nv_bfloat16* base0 = Ah + (size_t)m0 * K;
    const __nv_bfloat16* base1 = Al + (size_t)m0 * K;
    const __nv_bfloat16* base2 = Bh + (size_t)n0 * K;
    const __nv_bfloat16* base3 = Bl + (size_t)n0 * K;

    uint32_t sbase = (uint32_t)__cvta_generic_to_shared(dsm);
    // ldmatrix per-lane row/col components (element units)
    int a_row = wr * 64 + (lane & 15);
    int a_colx = (lane >> 4) << 3;               // 0 or 8
    int b_row = wc * 32 + (lane & 7) + ((lane & 16) ? 8 : 0);
    int b_colx = (lane & 8);                     // 0 or 8

    float acc[4][4][4];
    #pragma unroll
    for (int i = 0; i < 4; i++)
        #pragma unroll
        for (int j = 0; j < 4; j++)
            #pragma unroll
            for (int q = 0; q < 4; q++) acc[i][j][q] = 0.f;

    #pragma unroll
    for (int i = 0; i < 2; i++) {
        int idx = tid + i * 256;
        int r = idx >> 2, q = idx & 3;
        size_t go = (size_t)r * K + q * 8;
        uint32_t so = sbase + (uint32_t)(r * SSTR32 + q * 8) * 2;
        cp16(so + 0 * TILE32 * 2, base0 + go);
        cp16(so + 1 * TILE32 * 2, base1 + go);
        cp16(so + 2 * TILE32 * 2, base2 + go);
        cp16(so + 3 * TILE32 * 2, base3 + go);
    }
    CP_COMMIT();

    const int T = K >> 5;
    for (int it = 0; it < T; it++) {
        if (it + 1 < T) {
            int k0n = (it + 1) << 5;
            uint32_t sb = sbase + ((it + 1) & 1) * STG32 * 2;
            #pragma unroll
            for (int i = 0; i < 2; i++) {
                int idx = tid + i * 256;
                int r = idx >> 2, q = idx & 3;
                size_t go = (size_t)r * K + q * 8 + k0n;
                uint32_t so = sb + (uint32_t)(r * SSTR32 + q * 8) * 2;
                cp16(so + 0 * TILE32 * 2, base0 + go);
                cp16(so + 1 * TILE32 * 2, base1 + go);
                cp16(so + 2 * TILE32 * 2, base2 + go);
                cp16(so + 3 * TILE32 * 2, base3 + go);
            }
            CP_COMMIT();
            CP_WAIT(1);
        } else {
            CP_WAIT(0);
        }
        __syncthreads();

        uint32_t st = sbase + (it & 1) * STG32 * 2;

        #pragma unroll
        for (int ks = 0; ks < 2; ks++) {
            uint32_t a_hi[4][4], a_lo[4][4], b_hi[4][2], b_lo[4][2];
            // A fragments: 4 mt tiles x {hi,lo}, one ldmatrix.x4 each
            uint32_t abase = st + (uint32_t)(a_row * SSTR32 + ks * 16 + a_colx) * 2;
            #pragma unroll
            for (int mt = 0; mt < 4; mt++) {
                uint32_t off = abase + (uint32_t)(mt * 16 * SSTR32) * 2;
                ldsm4(a_hi[mt], off);
                ldsm4(a_lo[mt], off + TILE32 * 2);
            }
            // B fragments: 2 nt-pairs x {hi,lo}
            uint32_t bbase = st + 2 * TILE32 * 2 +
                             (uint32_t)(b_row * SSTR32 + ks * 16 + b_colx) * 2;
            #pragma unroll
            for (int p = 0; p < 2; p++) {
                uint32_t off = bbase + (uint32_t)(p * 16 * SSTR32) * 2;
                uint32_t rb[4];
                ldsm4(rb, off);
                b_hi[2 * p][0] = rb[0]; b_hi[2 * p][1] = rb[1];
                b_hi[2 * p + 1][0] = rb[2]; b_hi[2 * p + 1][1] = rb[3];
                ldsm4(rb, off + TILE32 * 2);
                b_lo[2 * p][0] = rb[0]; b_lo[2 * p][1] = rb[1];
                b_lo[2 * p + 1][0] = rb[2]; b_lo[2 * p + 1][1] = rb[3];
            }
            #pragma unroll
            for (int mt = 0; mt < 4; mt++)
                #pragma unroll
                for (int nt = 0; nt < 4; nt++) {
                    mma16816(acc[mt][nt], a_hi[mt], b_hi[nt]);
                    mma16816(acc[mt][nt], a_hi[mt], b_lo[nt]);
                    mma16816(acc[mt][nt], a_lo[mt], b_hi[nt]);
                }
        }
        __syncthreads();
    }

    if (mode == 0) {
        if (blockIdx.x < 4) {
            // x half: stage tile in smem, fused causal conv(4)+bias+silu -> g_xc
            float* stage = (float*)dsm;   // 128 x SSTG fp32 = 67584 B <= 81920 B
            #pragma unroll
            for (int mt = 0; mt < 4; mt++)
                #pragma unroll
                for (int nt = 0; nt < 4; nt++) {
                    int row = wr * 64 + mt * 16 + g;
                    int col = wc * 32 + nt * 8 + tg * 2;
                    *(float2*)&stage[row * SSTG + col] =
                        make_float2(acc[mt][nt][0], acc[mt][nt][1]);
                    *(float2*)&stage[(row + 8) * SSTG + col] =
                        make_float2(acc[mt][nt][2], acc[mt][nt][3]);
                }
            __syncthreads();
            int dl = tid & 127;        // local channel
            int sh = tid >> 7;         // sequence half (0/1)
            int dg = n0 + dl;          // global channel
            float w0 = cw[dg * 4 + 0], w1 = cw[dg * 4 + 1];
            float w2 = cw[dg * 4 + 2], w3 = cw[dg * 4 + 3];
            float bias = cb[dg];
            float x0 = 0.f, x1 = 0.f, x2 = 0.f;
            const float* sp = stage + (sh * 64) * SSTG + dl;
            float* op = g_xc + (size_t)(m0 + sh * 64) * DI + dg;
            #pragma unroll 4
            for (int t = 0; t < LSEQ; t++) {
                float x3 = sp[t * SSTG];
                float a = fmaf(w3, x3, fmaf(w2, x2, fmaf(w1, x1, fmaf(w0, x0, bias))));
                op[t * DI] = siluf(a);
                x0 = x1; x1 = x2; x2 = x3;
            }
        } else {
            gemm_epilogue(acc, g_z, DI, m0, n0 - 512, wr, wc, g, tg);
        }
    } else {
        gemm_epilogue(acc, g_tmp, CDIM, m0, n0, wr, wc, g, tg);
    }
}

// ---------------- fallback: BK=16, static smem (no conv fusion) ----------------
#define SSTR 24
#define TILE_E (128 * SSTR)
#define STAGE_E (4 * TILE_E)
__global__ void __launch_bounds__(256, 2) k_mma_gemm16(int mode) {
    __shared__ __align__(16) __nv_bfloat16 smem[2 * STAGE_E];

    const __nv_bfloat16 *Ah, *Al, *Bh, *Bl;
    int K;
    gemm_cfg(mode, Ah, Al, Bh, Bl, K);

    int tid = threadIdx.x, warp = tid >> 5, lane = tid & 31;
    int wr = warp >> 2, wc = warp & 3;
    int g = lane >> 2, tg = lane & 3;
    int m0 = blockIdx.y * 128, n0 = blockIdx.x * 128;

    const __nv_bfloat16* base0 = Ah + (size_t)m0 * K;
    const __nv_bfloat16* base1 = Al + (size_t)m0 * K;
    const __nv_bfloat16* base2 = Bh + (size_t)n0 * K;
    const __nv_bfloat16* base3 = Bl + (size_t)n0 * K;

    uint32_t sbase = (uint32_t)__cvta_generic_to_shared(smem);
    int lr = tid >> 1, lq = tid & 1;
    size_t goff = (size_t)lr * K + lq * 8;
    uint32_t soff = (uint32_t)(lr * SSTR + lq * 8) * 2;

    float acc[4][4][4];
    #pragma unroll
    for (int i = 0; i < 4; i++)
        #pragma unroll
        for (int j = 0; j < 4; j++)
            #pragma unroll
            for (int q = 0; q < 4; q++) acc[i][j][q] = 0.f;

    {
        uint32_t sb = sbase + soff;
        cp16(sb + 0 * TILE_E * 2, base0 + goff);
        cp16(sb + 1 * TILE_E * 2, base1 + goff);
        cp16(sb + 2 * TILE_E * 2, base2 + goff);
        cp16(sb + 3 * TILE_E * 2, base3 + goff);
        CP_COMMIT();
    }

    const int T = K >> 4;
    for (int it = 0; it < T; it++) {
        if (it + 1 < T) {
            int k0n = (it + 1) << 4;
            uint32_t sb = sbase + ((it + 1) & 1) * STAGE_E * 2 + soff;
            cp16(sb + 0 * TILE_E * 2, base0 + goff + k0n);
            cp16(sb + 1 * TILE_E * 2, base1 + goff + k0n);
            cp16(sb + 2 * TILE_E * 2, base2 + goff + k0n);
            cp16(sb + 3 * TILE_E * 2, base3 + goff + k0n);
            CP_COMMIT();
            CP_WAIT(1);
        } else {
            CP_WAIT(0);
        }
        __syncthreads();

        const __nv_bfloat16* s0 = smem + (it & 1) * STAGE_E;
        const __nv_bfloat16* sAh = s0;
        const __nv_bfloat16* sAl = s0 + TILE_E;
        const __nv_bfloat16* sBh = s0 + 2 * TILE_E;
        const __nv_bfloat16* sBl = s0 + 3 * TILE_E;
        int kb = tg * 2;

        uint32_t a_hi[4][4], a_lo[4][4], b_hi[4][2], b_lo[4][2];
        #pragma unroll
        for (int mt = 0; mt < 4; mt++) {
            int row = wr * 64 + mt * 16 + g;
            a_hi[mt][0] = *(const uint32_t*)&sAh[row * SSTR + kb];
            a_hi[mt][1] = *(const uint32_t*)&sAh[(row + 8) * SSTR + kb];
            a_hi[mt][2] = *(const uint32_t*)&sAh[row * SSTR + kb + 8];
            a_hi[mt][3] = *(const uint32_t*)&sAh[(row + 8) * SSTR + kb + 8];
            a_lo[mt][0] = *(const uint32_t*)&sAl[row * SSTR + kb];
            a_lo[mt][1] = *(const uint32_t*)&sAl[(row + 8) * SSTR + kb];
            a_lo[mt][2] = *(const uint32_t*)&sAl[row * SSTR + kb + 8];
            a_lo[mt][3] = *(const uint32_t*)&sAl[(row + 8) * SSTR + kb + 8];
        }
        #pragma unroll
        for (int nt = 0; nt < 4; nt++) {
            int rn = wc * 32 + nt * 8 + g;
            b_hi[nt][0] = *(const uint32_t*)&sBh[rn * SSTR + kb];
            b_hi[nt][1] = *(const uint32_t*)&sBh[rn * SSTR + kb + 8];
            b_lo[nt][0] = *(const uint32_t*)&sBl[rn * SSTR + kb];
            b_lo[nt][1] = *(const uint32_t*)&sBl[rn * SSTR + kb + 8];
        }
        #pragma unroll
        for (int mt = 0; mt < 4; mt++)
            #pragma unroll
            for (int nt = 0; nt < 4; nt++) {
                mma16816(acc[mt][nt], a_hi[mt], b_hi[nt]);
                mma16816(acc[mt][nt], a_hi[mt], b_lo[nt]);
                mma16816(acc[mt][nt], a_lo[mt], b_hi[nt]);
            }
        __syncthreads();
    }
    if (mode == 0) {
        if (blockIdx.x < 4) gemm_epilogue(acc, g_xraw, DI, m0, n0, wr, wc, g, tg);
        else                gemm_epilogue(acc, g_z, DI, m0, n0 - 512, wr, wc, g, tg);
    } else {
        gemm_epilogue(acc, g_tmp, CDIM, m0, n0, wr, wc, g, tg);
    }
}

// ---------------- depthwise conv(4, causal) + bias + silu (FALLBACK path only) ----------------
__global__ void k_conv_silu(const float* __restrict__ cw, const float* __restrict__ cb) {
    int s = blockIdx.x;
    int d = blockIdx.y * 128 + threadIdx.x;
    float w0 = cw[d * 4 + 0], w1 = cw[d * 4 + 1], w2 = cw[d * 4 + 2], w3 = cw[d * 4 + 3];
    float bias = cb[d];
    float x0 = 0.f, x1 = 0.f, x2 = 0.f;
    const float* xp = g_xraw + (size_t)s * LSEQ * DI + d;
    float*       op = g_xc   + (size_t)s * LSEQ * DI + d;
    #pragma unroll 4
    for (int t = 0; t < LSEQ; t++) {
        float x3 = xp[t * DI];
        float a = fmaf(w3, x3, fmaf(w2, x2, fmaf(w1, x1, fmaf(w0, x0, bias))));
        op[t * DI] = siluf(a);
        x0 = x1; x1 = x2; x2 = x3;
    }
}

// ---------------- x-proj GEMM: g_dbc[m, 0:48] = g_xc[m,:] @ W_xproj ----------------
__global__ void __launch_bounds__(256) k_xproj(const float* __restrict__ Wx) {
    __shared__ __align__(16) float As[32][68];
    __shared__ float Bs[32][48];
    int m0 = blockIdx.x * 64;
    int tid = threadIdx.x;
    int rg = tid & 15;
    int cg = tid >> 4;
    float acc[4][3];
    #pragma unroll
    for (int i = 0; i < 4; i++)
        #pragma unroll
        for (int j = 0; j < 3; j++) acc[i][j] = 0.f;

    for (int k0 = 0; k0 < DI; k0 += 32) {
        #pragma unroll
        for (int i = 0; i < 2; i++) {
            int idx = tid + i * 256;
            int r = idx >> 3, kc = (idx & 7) * 4;
            float4 v = *(const float4*)&g_xc[(size_t)(m0 + r) * DI + k0 + kc];
            As[kc + 0][r] = v.x; As[kc + 1][r] = v.y;
            As[kc + 2][r] = v.z; As[kc + 3][r] = v.w;
        }
        #pragma unroll
        for (int i = 0; i < 6; i++) {
            int idx = tid + i * 256;
            int k = idx / 48, n = idx % 48;
            Bs[k][n] = Wx[(k0 + k) * NXP + n];
        }
        __syncthreads();
        #pragma unroll
        for (int k = 0; k < 32; k++) {
            float4 a = *(const float4*)&As[k][rg * 4];
            float b0 = Bs[k][cg * 3 + 0];
            float b1 = Bs[k][cg * 3 + 1];
            float b2 = Bs[k][cg * 3 + 2];
            acc[0][0] = fmaf(a.x, b0, acc[0][0]);
            acc[0][1] = fmaf(a.x, b1, acc[0][1]);
            acc[0][2] = fmaf(a.x, b2, acc[0][2]);
            acc[1][0] = fmaf(a.y, b0, acc[1][0]);
            acc[1][1] = fmaf(a.y, b1, acc[1][1]);
            acc[1][2] = fmaf(a.y, b2, acc[1][2]);
            acc[2][0] = fmaf(a.z, b0, acc[2][0]);
            acc[2][1] = fmaf(a.z, b1, acc[2][1]);
            acc[2][2] = fmaf(a.z, b2, acc[2][2]);
            acc[3][0] = fmaf(a.w, b0, acc[3][0]);
            acc[3][1] = fmaf(a.w, b1, acc[3][1]);
            acc[3][2] = fmaf(a.w, b2, acc[3][2]);
        }
        __syncthreads();
    }
    #pragma unroll
    for (int i = 0; i < 4; i++)
        #pragma unroll
        for (int j = 0; j < 3; j++)
            g_dbc[(size_t)(m0 + rg * 4 + i) * NXP + cg * 3 + j] = acc[i][j];
}

// ---------------- selective scan (dt-proj fused; exp-recurrence; writes y+xc*D) ----------------
__global__ void __launch_bounds__(512) k_scan(const float* __restrict__ Alog,
                                              const float* __restrict__ Wdt,
                                              const float* __restrict__ bdt,
                                              const float* __restrict__ Dp) {
    __shared__ float Rs[LSEQ][DTR];
    __shared__ float Bs[LSEQ][DST];
    __shared__ float Cs[LSEQ][DST];
    int s = blockIdx.x;
    int d = threadIdx.x;
    for (int i = threadIdx.x; i < LSEQ * NXP; i += 512) {
        int t = i / NXP, j = i % NXP;
        float v = g_dbc[(size_t)(s * LSEQ + t) * NXP + j];
        if (j < DTR) Rs[t][j] = v;
        else if (j < DTR + DST) Bs[t][j - DTR] = v;
        else Cs[t][j - DTR - DST] = v;
    }
    __syncthreads();
    float A[DST], h[DST], w[DTR];
    bool fast = true;
    #pragma unroll
    for (int n = 0; n < DST; n++) {
        A[n] = -expf(Alog[d * DST + n]);
        h[n] = 0.f;
        fast = fast && (fabsf(A[n] + (float)(n + 1)) <= 1e-3f * (float)(n + 1));
    }
    #pragma unroll
    for (int i = 0; i < DTR; i++) w[i] = Wdt[i * DI + d];
    float bd = bdt[d];
    float Dd = Dp[d];
    const float* xp = g_xc + (size_t)s * LSEQ * DI + d;
    float*       yp = g_y  + (size_t)s * LSEQ * DI + d;

    if (fast) {
        for (int t = 0; t < LSEQ; t++) {
            float acc = bd;
            #pragma unroll
            for (int i = 0; i < DTR; i++) acc = fmaf(Rs[t][i], w[i], acc);
            float dt = softplusf(acc);
            float xc = xp[t * DI];
            float dtx = dt * xc;
            float r = __expf(-dt);
            float y = 0.f, p = 1.f;
            #pragma unroll
            for (int n = 0; n < DST; n++) {
                p *= r;
                h[n] = fmaf(p, h[n], dtx * Bs[t][n]);
                y = fmaf(h[n], Cs[t][n], y);
            }
            yp[t * DI] = fmaf(xc, Dd, y);
        }
    } else {
        for (int t = 0; t < LSEQ; t++) {
            float acc = bd;
            #pragma unroll
            for (int i = 0; i < DTR; i++) acc = fmaf(Rs[t][i], w[i], acc);
            float dt = softplusf(acc);
            float xc = xp[t * DI];
            float dtx = dt * xc;
            float y = 0.f;
            #pragma unroll
            for (int n = 0; n < DST; n++) {
                float dA = __expf(dt * A[n]);
                h[n] = fmaf(dA, h[n], dtx * Bs[t][n]);
                y = fmaf(h[n], Cs[t][n], y);
            }
            yp[t * DI] = fmaf(xc, Dd, y);
        }
    }
}

// ---------------- gate: yb16 = y * silu(z), float4-vectorized ----------------
__global__ void k_gate(int dummy) {
    size_t i = ((size_t)blockIdx.x * 256 + threadIdx.x) * 4;
    float4 y = *(const float4*)&g_y[i];
    float4 z = *(const float4*)&g_z[i];
    float v0 = y.x * siluf(z.x);
    float v1 = y.y * siluf(z.y);
    float v2 = y.z * siluf(z.z);
    float v3 = y.w * siluf(z.w);
    __nv_bfloat16 h0 = __float2bfloat16(v0), h1 = __float2bfloat16(v1);
    __nv_bfloat16 h2 = __float2bfloat16(v2), h3 = __float2bfloat16(v3);
    __nv_bfloat16 hv[4] = {h0, h1, h2, h3};
    __nv_bfloat16 lv[4] = {
        __float2bfloat16(v0 - __bfloat162float(h0)),
        __float2bfloat16(v1 - __bfloat162float(h1)),
        __float2bfloat16(v2 - __bfloat162float(h2)),
        __float2bfloat16(v3 - __bfloat162float(h3))};
    *(uint2*)&g_yh[i] = *(const uint2*)hv;
    *(uint2*)&g_yl[i] = *(const uint2*)lv;
}

// ---------------- scatter g_tmp -> out(b,c,h,w) ----------------
__global__ void k_scatter(float* __restrict__ out, int dir, int accum) {
    __shared__ float tile[32][33];
    int rt = blockIdx.x, ct = blockIdx.y, b = blockIdx.z;
    int tx = threadIdx.x, ty = threadIdx.y;
    int c0 = ct * 32;
    if (dir == 0) {
        int rem0 = rt * 32;
        #pragma unroll
        for (int i = 0; i < 4; i++) {
            int rem = rem0 + ty + i * 8;
            tile[ty + i * 8][tx] = g_tmp[(size_t)(b * 4096 + rem) * CDIM + c0 + tx];
        }
        __syncthreads();
        #pragma unroll
        for (int i = 0; i < 4; i++) {
            int c = c0 + ty + i * 8;
            size_t o = (size_t)(b * 256 + c) * 4096 + rem0 + tx;
            float v = tile[tx][ty + i * 8];
            if (accum) out[o] += v; else out[o] = v;
        }
    } else {
        int h = rt >> 1, w0 = (rt & 1) * 32;
        #pragma unroll
        for (int i = 0; i < 4; i++) {
            int w = w0 + ty + i * 8;
            tile[ty + i * 8][tx] = g_tmp[(size_t)(b * 4096 + w * 64 + h) * CDIM + c0 + tx];
        }
        __syncthreads();
        #pragma unroll
        for (int i = 0; i < 4; i++) {
            int c = c0 + ty + i * 8;
            size_t o = (size_t)(b * 256 + c) * 4096 + h * 64 + w0 + tx;
            float v = tile[tx][ty + i * 8];
            if (accum) out[o] += v; else out[o] = v;
        }
    }
}

// ---------------- launch ----------------
extern "C" void kernel_launch(void* const* d_in, const int* in_sizes, int n_in,
                              void* d_out, int out_size) {
    const float* x = (const float*)d_in[0];
    float* out = (float*)d_out;

    cudaError_t e = cudaFuncSetAttribute(k_mma_gemm32,
        cudaFuncAttributeMaxDynamicSharedMemorySize, 2 * STG32 * 2);
    bool use32 = (e == cudaSuccess);
    cudaGetLastError();

    k_transpose_hw<<<dim3(2, 2, 2048), dim3(32, 8)>>>(x);

    for (int dir = 0; dir < 2; dir++) {
        const float* Win  = (const float*)d_in[1 + dir * 9 + 0];
        const float* cw   = (const float*)d_in[1 + dir * 9 + 1];
        const float* cb   = (const float*)d_in[1 + dir * 9 + 2];
        const float* Wx   = (const float*)d_in[1 + dir * 9 + 3];
        const float* Wdt  = (const float*)d_in[1 + dir * 9 + 4];
        const float* bdt  = (const float*)d_in[1 + dir * 9 + 5];
        const float* Alog = (const float*)d_in[1 + dir * 9 + 6];
        const float* Dp   = (const float*)d_in[1 + dir * 9 + 7];
        const float* Wout = (const float*)d_in[1 + dir * 9 + 8];

        k_convA<<<dim3(128, 8, 8), dim3(32, 8)>>>(x, dir);
        k_convW<<<dim3(1024 / 32, 256 / 32), dim3(32, 8)>>>(Win, 256, 1024, 0);
        if (use32) {
            k_mma_gemm32<<<dim3(8, 256), 256, 2 * STG32 * 2>>>(0, cw, cb);
        } else {
            k_mma_gemm16<<<dim3(8, 256), 256>>>(0);
            k_conv_silu<<<dim3(NSEQ, 4), 128>>>(cw, cb);
        }
        k_xproj<<<MDIM / 64, 256>>>(Wx);
        k_scan<<<NSEQ, 512>>>(Alog, Wdt, bdt, Dp);
        k_gate<<<(MDIM * DI) / 1024, 256>>>(0);
        k_convW<<<dim3(256 / 32, 512 / 32), dim3(32, 8)>>>(Wout, 512, 256, 1);
        if (use32) k_mma_gemm32<<<dim3(2, 256), 256, 2 * STG32 * 2>>>(1, nullptr, nullptr);
        else       k_mma_gemm16<<<dim3(2, 256), 256>>>(1);
        k_scatter<<<dim3(128, 8, 8), dim3(32, 8)>>>(out, dir, dir);
    }
}

// round 13
// speedup vs baseline: 1.2650x; 1.1213x over previous
#include <cuda_runtime.h>
#include <cuda_bf16.h>
#include <cstdint>
#include <math.h>

// ---------------- problem constants ----------------
#define NSEQ   512
#define LSEQ   64
#define MDIM   (NSEQ*LSEQ)  // 32768
#define CDIM   256
#define DI     512
#define NXZ    1024
#define DST    16
#define DTR    16
#define NXP    48

#define AOFF   (MDIM * 256)   // per-dir A (bf16) elems
#define XOFF   (MDIM * DI)    // per-dir x/z/y elems
#define TOFF   (MDIM * CDIM)  // per-dir tmp elems
#define DBCOFF (MDIM * NXP)

// ---------------- scratch (device symbols; both dirs batched) ----------------
__device__ float g_z   [2 * XOFF];
__device__ float g_xraw[2 * XOFF];      // fallback path only
__device__ float g_xc  [2 * XOFF];
__device__ float g_dbc [2 * DBCOFF];
__device__ float g_y   [2 * XOFF];
__device__ float g_tmp [2 * TOFF];
__device__ float g_xT  [8 * 256 * 64 * 64];
__device__ __nv_bfloat16 g_ah [2 * AOFF];
__device__ __nv_bfloat16 g_al [2 * AOFF];
__device__ __nv_bfloat16 g_yh [2 * XOFF];
__device__ __nv_bfloat16 g_yl [2 * XOFF];
__device__ __nv_bfloat16 g_wtih[2 * 1024 * 256];
__device__ __nv_bfloat16 g_wtil[2 * 1024 * 256];
__device__ __nv_bfloat16 g_wtoh[2 * 256 * 512];
__device__ __nv_bfloat16 g_wtol[2 * 256 * 512];

__device__ __forceinline__ float siluf(float v)    { return v / (1.f + __expf(-v)); }
__device__ __forceinline__ float softplusf(float v){ return (v > 20.f) ? v : log1pf(expf(v)); }

// ---------------- mma.sync / cp.async / ldmatrix helpers ----------------
__device__ __forceinline__ void mma16816(float* c, const uint32_t* a, const uint32_t* b) {
    asm volatile(
        "mma.sync.aligned.m16n8k16.row.col.f32.bf16.bf16.f32 "
        "{%0,%1,%2,%3}, {%4,%5,%6,%7}, {%8,%9}, {%0,%1,%2,%3};\n"
        : "+f"(c[0]), "+f"(c[1]), "+f"(c[2]), "+f"(c[3])
        : "r"(a[0]), "r"(a[1]), "r"(a[2]), "r"(a[3]), "r"(b[0]), "r"(b[1]));
}
__device__ __forceinline__ void cp16(uint32_t saddr, const void* g) {
    asm volatile("cp.async.cg.shared.global [%0], [%1], 16;" :: "r"(saddr), "l"(g));
}
__device__ __forceinline__ void ldsm4(uint32_t* r, uint32_t saddr) {
    asm volatile("ldmatrix.sync.aligned.m8n8.x4.shared.b16 {%0,%1,%2,%3}, [%4];"
        : "=r"(r[0]), "=r"(r[1]), "=r"(r[2]), "=r"(r[3]) : "r"(saddr));
}
#define CP_COMMIT() asm volatile("cp.async.commit_group;" ::: "memory")
#define CP_WAIT(n)  asm volatile("cp.async.wait_group %0;" :: "n"(n) : "memory")

// ---------------- transpose x(b,c,h,w) -> xT(b,c,w,h) ----------------
__global__ void k_transpose_hw(const float* __restrict__ x) {
    __shared__ float tile[32][33];
    int bc = blockIdx.z, ht = blockIdx.y, wt = blockIdx.x;
    const float* src = x    + (size_t)bc * 4096;
    float*       dst = g_xT + (size_t)bc * 4096;
    int tx = threadIdx.x, ty = threadIdx.y;
    #pragma unroll
    for (int i = 0; i < 4; i++) {
        int h = ht * 32 + ty + i * 8;
        tile[ty + i * 8][tx] = src[h * 64 + wt * 32 + tx];
    }
    __syncthreads();
    #pragma unroll
    for (int i = 0; i < 4; i++) {
        int w = wt * 32 + ty + i * 8;
        dst[w * 64 + ht * 32 + tx] = tile[tx][ty + i * 8];
    }
}

// ---------------- convert A (both dirs): -> bf16 hi/lo [dir][m][k] ----------------
__global__ void k_convA(const float* __restrict__ xin) {
    __shared__ float t[32][33];
    int z = blockIdx.z;            // dir*8 + b
    int dir = z >> 3, b = z & 7;
    const float* src = dir ? g_xT : xin;
    int kt = blockIdx.y, rt = blockIdx.x;
    int tx = threadIdx.x, ty = threadIdx.y;
    #pragma unroll
    for (int i = 0; i < 4; i++) {
        int k = kt * 32 + ty + i * 8;
        t[ty + i * 8][tx] = src[(size_t)(b * 256 + k) * 4096 + rt * 32 + tx];
    }
    __syncthreads();
    size_t dofs = (size_t)dir * AOFF;
    #pragma unroll
    for (int i = 0; i < 4; i++) {
        int rem = rt * 32 + ty + i * 8;
        size_t m = (size_t)b * 4096 + rem;
        float v = t[tx][ty + i * 8];
        __nv_bfloat16 h = __float2bfloat16(v);
        g_ah[dofs + m * 256 + kt * 32 + tx] = h;
        g_al[dofs + m * 256 + kt * 32 + tx] = __float2bfloat16(v - __bfloat162float(h));
    }
}

// ---------------- convert+transpose weights (both dirs) ----------------
__global__ void k_convW(const float* __restrict__ W0, const float* __restrict__ W1,
                        int R, int C, int which) {
    __shared__ float t[32][33];
    int dir = blockIdx.z;
    const float* W = dir ? W1 : W0;
    size_t dofs = (size_t)dir * R * C;
    __nv_bfloat16* Th = (which ? g_wtoh : g_wtih) + dofs;
    __nv_bfloat16* Tl = (which ? g_wtol : g_wtil) + dofs;
    int r0 = blockIdx.y * 32, c0 = blockIdx.x * 32;
    int tx = threadIdx.x, ty = threadIdx.y;
    #pragma unroll
    for (int i = 0; i < 4; i++)
        t[ty + i * 8][tx] = W[(size_t)(r0 + ty + i * 8) * C + c0 + tx];
    __syncthreads();
    #pragma unroll
    for (int i = 0; i < 4; i++) {
        float v = t[tx][ty + i * 8];
        int oc = c0 + ty + i * 8;
        __nv_bfloat16 h = __float2bfloat16(v);
        Th[(size_t)oc * R + r0 + tx] = h;
        Tl[(size_t)oc * R + r0 + tx] = __float2bfloat16(v - __bfloat162float(h));
    }
}

__device__ __forceinline__ void gemm_epilogue(float acc[4][4][4], float* Cout, int ldc,
                                              int m0, int n0, int wr, int wc, int g, int tg)
{
    #pragma unroll
    for (int mt = 0; mt < 4; mt++)
        #pragma unroll
        for (int nt = 0; nt < 4; nt++) {
            int row = m0 + wr * 64 + mt * 16 + g;
            int col = n0 + wc * 32 + nt * 8 + tg * 2;
            *(float2*)&Cout[(size_t)row * ldc + col] =
                make_float2(acc[mt][nt][0], acc[mt][nt][1]);
            *(float2*)&Cout[(size_t)(row + 8) * ldc + col] =
                make_float2(acc[mt][nt][2], acc[mt][nt][3]);
        }
}

// ---------------- HMMA bf16x3 GEMM, BK=32, cp.async 2-stage, ldmatrix, batched dirs ----------------
#define SSTR32 40
#define TILE32 (128 * SSTR32)
#define STG32  (4 * TILE32)
#define SSTG   132
__global__ void __launch_bounds__(256, 2) k_mma_gemm32(int mode,
        const float* __restrict__ cw0, const float* __restrict__ cb0,
        const float* __restrict__ cw1, const float* __restrict__ cb1) {
    extern __shared__ __nv_bfloat16 dsm[];

    int dir = blockIdx.z;
    const __nv_bfloat16 *Ah, *Al, *Bh, *Bl;
    int K;
    if (mode == 0) {
        K = 256;
        Ah = g_ah + (size_t)dir * AOFF;  Al = g_al + (size_t)dir * AOFF;
        Bh = g_wtih + (size_t)dir * 1024 * 256;
        Bl = g_wtil + (size_t)dir * 1024 * 256;
    } else {
        K = 512;
        Ah = g_yh + (size_t)dir * XOFF;  Al = g_yl + (size_t)dir * XOFF;
        Bh = g_wtoh + (size_t)dir * 256 * 512;
        Bl = g_wtol + (size_t)dir * 256 * 512;
    }

    int tid = threadIdx.x, warp = tid >> 5, lane = tid & 31;
    int wr = warp >> 2, wc = warp & 3;
    int g = lane >> 2, tg = lane & 3;
    int m0 = blockIdx.y * 128, n0 = blockIdx.x * 128;

    const __nv_bfloat16* base0 = Ah + (size_t)m0 * K;
    const __nv_bfloat16* base1 = Al + (size_t)m0 * K;
    const __nv_bfloat16* base2 = Bh + (size_t)n0 * K;
    const __nv_bfloat16* base3 = Bl + (size_t)n0 * K;

    uint32_t sbase = (uint32_t)__cvta_generic_to_shared(dsm);
    int a_row = wr * 64 + (lane & 15);
    int a_colx = (lane >> 4) << 3;
    int b_row = wc * 32 + (lane & 7) + ((lane & 16) ? 8 : 0);
    int b_colx = (lane & 8);

    float acc[4][4][4];
    #pragma unroll
    for (int i = 0; i < 4; i++)
        #pragma unroll
        for (int j = 0; j < 4; j++)
            #pragma unroll
            for (int q = 0; q < 4; q++) acc[i][j][q] = 0.f;

    #pragma unroll
    for (int i = 0; i < 2; i++) {
        int idx = tid + i * 256;
        int r = idx >> 2, q = idx & 3;
        size_t go = (size_t)r * K + q * 8;
        uint32_t so = sbase + (uint32_t)(r * SSTR32 + q * 8) * 2;
        cp16(so + 0 * TILE32 * 2, base0 + go);
        cp16(so + 1 * TILE32 * 2, base1 + go);
        cp16(so + 2 * TILE32 * 2, base2 + go);
        cp16(so + 3 * TILE32 * 2, base3 + go);
    }
    CP_COMMIT();

    const int T = K >> 5;
    for (int it = 0; it < T; it++) {
        if (it + 1 < T) {
            int k0n = (it + 1) << 5;
            uint32_t sb = sbase + ((it + 1) & 1) * STG32 * 2;
            #pragma unroll
            for (int i = 0; i < 2; i++) {
                int idx = tid + i * 256;
                int r = idx >> 2, q = idx & 3;
                size_t go = (size_t)r * K + q * 8 + k0n;
                uint32_t so = sb + (uint32_t)(r * SSTR32 + q * 8) * 2;
                cp16(so + 0 * TILE32 * 2, base0 + go);
                cp16(so + 1 * TILE32 * 2, base1 + go);
                cp16(so + 2 * TILE32 * 2, base2 + go);
                cp16(so + 3 * TILE32 * 2, base3 + go);
            }
            CP_COMMIT();
            CP_WAIT(1);
        } else {
            CP_WAIT(0);
        }
        __syncthreads();

        uint32_t st = sbase + (it & 1) * STG32 * 2;

        #pragma unroll
        for (int ks = 0; ks < 2; ks++) {
            uint32_t a_hi[4][4], a_lo[4][4], b_hi[4][2], b_lo[4][2];
            uint32_t abase = st + (uint32_t)(a_row * SSTR32 + ks * 16 + a_colx) * 2;
            #pragma unroll
            for (int mt = 0; mt < 4; mt++) {
                uint32_t off = abase + (uint32_t)(mt * 16 * SSTR32) * 2;
                ldsm4(a_hi[mt], off);
                ldsm4(a_lo[mt], off + TILE32 * 2);
            }
            uint32_t bbase = st + 2 * TILE32 * 2 +
                             (uint32_t)(b_row * SSTR32 + ks * 16 + b_colx) * 2;
            #pragma unroll
            for (int p = 0; p < 2; p++) {
                uint32_t off = bbase + (uint32_t)(p * 16 * SSTR32) * 2;
                uint32_t rb[4];
                ldsm4(rb, off);
                b_hi[2 * p][0] = rb[0]; b_hi[2 * p][1] = rb[1];
                b_hi[2 * p + 1][0] = rb[2]; b_hi[2 * p + 1][1] = rb[3];
                ldsm4(rb, off + TILE32 * 2);
                b_lo[2 * p][0] = rb[0]; b_lo[2 * p][1] = rb[1];
                b_lo[2 * p + 1][0] = rb[2]; b_lo[2 * p + 1][1] = rb[3];
            }
            #pragma unroll
            for (int mt = 0; mt < 4; mt++)
                #pragma unroll
                for (int nt = 0; nt < 4; nt++) {
                    mma16816(acc[mt][nt], a_hi[mt], b_hi[nt]);
                    mma16816(acc[mt][nt], a_hi[mt], b_lo[nt]);
                    mma16816(acc[mt][nt], a_lo[mt], b_hi[nt]);
                }
        }
        __syncthreads();
    }

    if (mode == 0) {
        if (blockIdx.x < 4) {
            float* stage = (float*)dsm;
            #pragma unroll
            for (int mt = 0; mt < 4; mt++)
                #pragma unroll
                for (int nt = 0; nt < 4; nt++) {
                    int row = wr * 64 + mt * 16 + g;
                    int col = wc * 32 + nt * 8 + tg * 2;
                    *(float2*)&stage[row * SSTG + col] =
                        make_float2(acc[mt][nt][0], acc[mt][nt][1]);
                    *(float2*)&stage[(row + 8) * SSTG + col] =
                        make_float2(acc[mt][nt][2], acc[mt][nt][3]);
                }
            __syncthreads();
            const float* cw = dir ? cw1 : cw0;
            const float* cb = dir ? cb1 : cb0;
            int dl = tid & 127;
            int sh = tid >> 7;
            int dg = n0 + dl;
            float w0 = cw[dg * 4 + 0], w1 = cw[dg * 4 + 1];
            float w2 = cw[dg * 4 + 2], w3 = cw[dg * 4 + 3];
            float bias = cb[dg];
            float x0 = 0.f, x1 = 0.f, x2 = 0.f;
            const float* sp = stage + (sh * 64) * SSTG + dl;
            float* op = g_xc + (size_t)dir * XOFF + (size_t)(m0 + sh * 64) * DI + dg;
            #pragma unroll 4
            for (int t = 0; t < LSEQ; t++) {
                float x3 = sp[t * SSTG];
                float a = fmaf(w3, x3, fmaf(w2, x2, fmaf(w1, x1, fmaf(w0, x0, bias))));
                op[t * DI] = siluf(a);
                x0 = x1; x1 = x2; x2 = x3;
            }
        } else {
            gemm_epilogue(acc, g_z + (size_t)dir * XOFF, DI, m0, n0 - 512, wr, wc, g, tg);
        }
    } else {
        gemm_epilogue(acc, g_tmp + (size_t)dir * TOFF, CDIM, m0, n0, wr, wc, g, tg);
    }
}

// ---------------- fallback: BK=16, static smem, batched dirs (no conv fusion) ----------------
#define SSTR 24
#define TILE_E (128 * SSTR)
#define STAGE_E (4 * TILE_E)
__global__ void __launch_bounds__(256, 2) k_mma_gemm16(int mode) {
    __shared__ __align__(16) __nv_bfloat16 smem[2 * STAGE_E];

    int dir = blockIdx.z;
    const __nv_bfloat16 *Ah, *Al, *Bh, *Bl;
    int K;
    if (mode == 0) {
        K = 256;
        Ah = g_ah + (size_t)dir * AOFF;  Al = g_al + (size_t)dir * AOFF;
        Bh = g_wtih + (size_t)dir * 1024 * 256;
        Bl = g_wtil + (size_t)dir * 1024 * 256;
    } else {
        K = 512;
        Ah = g_yh + (size_t)dir * XOFF;  Al = g_yl + (size_t)dir * XOFF;
        Bh = g_wtoh + (size_t)dir * 256 * 512;
        Bl = g_wtol + (size_t)dir * 256 * 512;
    }

    int tid = threadIdx.x, warp = tid >> 5, lane = tid & 31;
    int wr = warp >> 2, wc = warp & 3;
    int g = lane >> 2, tg = lane & 3;
    int m0 = blockIdx.y * 128, n0 = blockIdx.x * 128;

    const __nv_bfloat16* base0 = Ah + (size_t)m0 * K;
    const __nv_bfloat16* base1 = Al + (size_t)m0 * K;
    const __nv_bfloat16* base2 = Bh + (size_t)n0 * K;
    const __nv_bfloat16* base3 = Bl + (size_t)n0 * K;

    uint32_t sbase = (uint32_t)__cvta_generic_to_shared(smem);
    int lr = tid >> 1, lq = tid & 1;
    size_t goff = (size_t)lr * K + lq * 8;
    uint32_t soff = (uint32_t)(lr * SSTR + lq * 8) * 2;

    float acc[4][4][4];
    #pragma unroll
    for (int i = 0; i < 4; i++)
        #pragma unroll
        for (int j = 0; j < 4; j++)
            #pragma unroll
            for (int q = 0; q < 4; q++) acc[i][j][q] = 0.f;

    {
        uint32_t sb = sbase + soff;
        cp16(sb + 0 * TILE_E * 2, base0 + goff);
        cp16(sb + 1 * TILE_E * 2, base1 + goff);
        cp16(sb + 2 * TILE_E * 2, base2 + goff);
        cp16(sb + 3 * TILE_E * 2, base3 + goff);
        CP_COMMIT();
    }

    const int T = K >> 4;
    for (int it = 0; it < T; it++) {
        if (it + 1 < T) {
            int k0n = (it + 1) << 4;
            uint32_t sb = sbase + ((it + 1) & 1) * STAGE_E * 2 + soff;
            cp16(sb + 0 * TILE_E * 2, base0 + goff + k0n);
            cp16(sb + 1 * TILE_E * 2, base1 + goff + k0n);
            cp16(sb + 2 * TILE_E * 2, base2 + goff + k0n);
            cp16(sb + 3 * TILE_E * 2, base3 + goff + k0n);
            CP_COMMIT();
            CP_WAIT(1);
        } else {
            CP_WAIT(0);
        }
        __syncthreads();

        const __nv_bfloat16* s0 = smem + (it & 1) * STAGE_E;
        const __nv_bfloat16* sAh = s0;
        const __nv_bfloat16* sAl = s0 + TILE_E;
        const __nv_bfloat16* sBh = s0 + 2 * TILE_E;
        const __nv_bfloat16* sBl = s0 + 3 * TILE_E;
        int kb = tg * 2;

        uint32_t a_hi[4][4], a_lo[4][4], b_hi[4][2], b_lo[4][2];
        #pragma unroll
        for (int mt = 0; mt < 4; mt++) {
            int row = wr * 64 + mt * 16 + g;
            a_hi[mt][0] = *(const uint32_t*)&sAh[row * SSTR + kb];
            a_hi[mt][1] = *(const uint32_t*)&sAh[(row + 8) * SSTR + kb];
            a_hi[mt][2] = *(const uint32_t*)&sAh[row * SSTR + kb + 8];
            a_hi[mt][3] = *(const uint32_t*)&sAh[(row + 8) * SSTR + kb + 8];
            a_lo[mt][0] = *(const uint32_t*)&sAl[row * SSTR + kb];
            a_lo[mt][1] = *(const uint32_t*)&sAl[(row + 8) * SSTR + kb];
            a_lo[mt][2] = *(const uint32_t*)&sAl[row * SSTR + kb + 8];
            a_lo[mt][3] = *(const uint32_t*)&sAl[(row + 8) * SSTR + kb + 8];
        }
        #pragma unroll
        for (int nt = 0; nt < 4; nt++) {
            int rn = wc * 32 + nt * 8 + g;
            b_hi[nt][0] = *(const uint32_t*)&sBh[rn * SSTR + kb];
            b_hi[nt][1] = *(const uint32_t*)&sBh[rn * SSTR + kb + 8];
            b_lo[nt][0] = *(const uint32_t*)&sBl[rn * SSTR + kb];
            b_lo[nt][1] = *(const uint32_t*)&sBl[rn * SSTR + kb + 8];
        }
        #pragma unroll
        for (int mt = 0; mt < 4; mt++)
            #pragma unroll
            for (int nt = 0; nt < 4; nt++) {
                mma16816(acc[mt][nt], a_hi[mt], b_hi[nt]);
                mma16816(acc[mt][nt], a_hi[mt], b_lo[nt]);
                mma16816(acc[mt][nt], a_lo[mt], b_hi[nt]);
            }
        __syncthreads();
    }
    if (mode == 0) {
        if (blockIdx.x < 4) gemm_epilogue(acc, g_xraw + (size_t)dir * XOFF, DI, m0, n0, wr, wc, g, tg);
        else                gemm_epilogue(acc, g_z + (size_t)dir * XOFF, DI, m0, n0 - 512, wr, wc, g, tg);
    } else {
        gemm_epilogue(acc, g_tmp + (size_t)dir * TOFF, CDIM, m0, n0, wr, wc, g, tg);
    }
}

// ---------------- conv+silu (FALLBACK path only), batched dirs ----------------
__global__ void k_conv_silu(const float* __restrict__ cw0, const float* __restrict__ cb0,
                            const float* __restrict__ cw1, const float* __restrict__ cb1) {
    int dir = blockIdx.z;
    const float* cw = dir ? cw1 : cw0;
    const float* cb = dir ? cb1 : cb0;
    int s = blockIdx.x;
    int d = blockIdx.y * 128 + threadIdx.x;
    float w0 = cw[d * 4 + 0], w1 = cw[d * 4 + 1], w2 = cw[d * 4 + 2], w3 = cw[d * 4 + 3];
    float bias = cb[d];
    float x0 = 0.f, x1 = 0.f, x2 = 0.f;
    const float* xp = g_xraw + (size_t)dir * XOFF + (size_t)s * LSEQ * DI + d;
    float*       op = g_xc   + (size_t)dir * XOFF + (size_t)s * LSEQ * DI + d;
    #pragma unroll 4
    for (int t = 0; t < LSEQ; t++) {
        float x3 = xp[t * DI];
        float a = fmaf(w3, x3, fmaf(w2, x2, fmaf(w1, x1, fmaf(w0, x0, bias))));
        op[t * DI] = siluf(a);
        x0 = x1; x1 = x2; x2 = x3;
    }
}

// ---------------- x-proj GEMM, batched dirs ----------------
__global__ void __launch_bounds__(256) k_xproj(const float* __restrict__ Wx0,
                                               const float* __restrict__ Wx1) {
    __shared__ __align__(16) float As[32][68];
    __shared__ float Bs[32][48];
    int dir = blockIdx.y;
    const float* Wx = dir ? Wx1 : Wx0;
    const float* xc = g_xc + (size_t)dir * XOFF;
    float* dbc = g_dbc + (size_t)dir * DBCOFF;
    int m0 = blockIdx.x * 64;
    int tid = threadIdx.x;
    int rg = tid & 15;
    int cg = tid >> 4;
    float acc[4][3];
    #pragma unroll
    for (int i = 0; i < 4; i++)
        #pragma unroll
        for (int j = 0; j < 3; j++) acc[i][j] = 0.f;

    for (int k0 = 0; k0 < DI; k0 += 32) {
        #pragma unroll
        for (int i = 0; i < 2; i++) {
            int idx = tid + i * 256;
            int r = idx >> 3, kc = (idx & 7) * 4;
            float4 v = *(const float4*)&xc[(size_t)(m0 + r) * DI + k0 + kc];
            As[kc + 0][r] = v.x; As[kc + 1][r] = v.y;
            As[kc + 2][r] = v.z; As[kc + 3][r] = v.w;
        }
        #pragma unroll
        for (int i = 0; i < 6; i++) {
            int idx = tid + i * 256;
            int k = idx / 48, n = idx % 48;
            Bs[k][n] = Wx[(k0 + k) * NXP + n];
        }
        __syncthreads();
        #pragma unroll
        for (int k = 0; k < 32; k++) {
            float4 a = *(const float4*)&As[k][rg * 4];
            float b0 = Bs[k][cg * 3 + 0];
            float b1 = Bs[k][cg * 3 + 1];
            float b2 = Bs[k][cg * 3 + 2];
            acc[0][0] = fmaf(a.x, b0, acc[0][0]);
            acc[0][1] = fmaf(a.x, b1, acc[0][1]);
            acc[0][2] = fmaf(a.x, b2, acc[0][2]);
            acc[1][0] = fmaf(a.y, b0, acc[1][0]);
            acc[1][1] = fmaf(a.y, b1, acc[1][1]);
            acc[1][2] = fmaf(a.y, b2, acc[1][2]);
            acc[2][0] = fmaf(a.z, b0, acc[2][0]);
            acc[2][1] = fmaf(a.z, b1, acc[2][1]);
            acc[2][2] = fmaf(a.z, b2, acc[2][2]);
            acc[3][0] = fmaf(a.w, b0, acc[3][0]);
            acc[3][1] = fmaf(a.w, b1, acc[3][1]);
            acc[3][2] = fmaf(a.w, b2, acc[3][2]);
        }
        __syncthreads();
    }
    #pragma unroll
    for (int i = 0; i < 4; i++)
        #pragma unroll
        for (int j = 0; j < 3; j++)
            dbc[(size_t)(m0 + rg * 4 + i) * NXP + cg * 3 + j] = acc[i][j];
}

// ---------------- selective scan, batched dirs ----------------
__global__ void __launch_bounds__(512) k_scan(
    const float* __restrict__ Alog0, const float* __restrict__ Wdt0,
    const float* __restrict__ bdt0,  const float* __restrict__ Dp0,
    const float* __restrict__ Alog1, const float* __restrict__ Wdt1,
    const float* __restrict__ bdt1,  const float* __restrict__ Dp1) {
    __shared__ float Rs[LSEQ][DTR];
    __shared__ float Bs[LSEQ][DST];
    __shared__ float Cs[LSEQ][DST];
    int dir = blockIdx.y;
    const float* Alog = dir ? Alog1 : Alog0;
    const float* Wdt  = dir ? Wdt1  : Wdt0;
    const float* bdt  = dir ? bdt1  : bdt0;
    const float* Dp   = dir ? Dp1   : Dp0;
    const float* dbc  = g_dbc + (size_t)dir * DBCOFF;
    int s = blockIdx.x;
    int d = threadIdx.x;
    for (int i = threadIdx.x; i < LSEQ * NXP; i += 512) {
        int t = i / NXP, j = i % NXP;
        float v = dbc[(size_t)(s * LSEQ + t) * NXP + j];
        if (j < DTR) Rs[t][j] = v;
        else if (j < DTR + DST) Bs[t][j - DTR] = v;
        else Cs[t][j - DTR - DST] = v;
    }
    __syncthreads();
    float A[DST], h[DST], w[DTR];
    bool fast = true;
    #pragma unroll
    for (int n = 0; n < DST; n++) {
        A[n] = -expf(Alog[d * DST + n]);
        h[n] = 0.f;
        fast = fast && (fabsf(A[n] + (float)(n + 1)) <= 1e-3f * (float)(n + 1));
    }
    #pragma unroll
    for (int i = 0; i < DTR; i++) w[i] = Wdt[i * DI + d];
    float bd = bdt[d];
    float Dd = Dp[d];
    const float* xp = g_xc + (size_t)dir * XOFF + (size_t)s * LSEQ * DI + d;
    float*       yp = g_y  + (size_t)dir * XOFF + (size_t)s * LSEQ * DI + d;

    if (fast) {
        for (int t = 0; t < LSEQ; t++) {
            float acc = bd;
            #pragma unroll
            for (int i = 0; i < DTR; i++) acc = fmaf(Rs[t][i], w[i], acc);
            float dt = softplusf(acc);
            float xc = xp[t * DI];
            float dtx = dt * xc;
            float r = __expf(-dt);
            float y = 0.f, p = 1.f;
            #pragma unroll
            for (int n = 0; n < DST; n++) {
                p *= r;
                h[n] = fmaf(p, h[n], dtx * Bs[t][n]);
                y = fmaf(h[n], Cs[t][n], y);
            }
            yp[t * DI] = fmaf(xc, Dd, y);
        }
    } else {
        for (int t = 0; t < LSEQ; t++) {
            float acc = bd;
            #pragma unroll
            for (int i = 0; i < DTR; i++) acc = fmaf(Rs[t][i], w[i], acc);
            float dt = softplusf(acc);
            float xc = xp[t * DI];
            float dtx = dt * xc;
            float y = 0.f;
            #pragma unroll
            for (int n = 0; n < DST; n++) {
                float dA = __expf(dt * A[n]);
                h[n] = fmaf(dA, h[n], dtx * Bs[t][n]);
                y = fmaf(h[n], Cs[t][n], y);
            }
            yp[t * DI] = fmaf(xc, Dd, y);
        }
    }
}

// ---------------- gate: both dirs linear ----------------
__global__ void k_gate(int dummy) {
    size_t i = ((size_t)blockIdx.x * 256 + threadIdx.x) * 4;
    float4 y = *(const float4*)&g_y[i];
    float4 z = *(const float4*)&g_z[i];
    float v0 = y.x * siluf(z.x);
    float v1 = y.y * siluf(z.y);
    float v2 = y.z * siluf(z.z);
    float v3 = y.w * siluf(z.w);
    __nv_bfloat16 h0 = __float2bfloat16(v0), h1 = __float2bfloat16(v1);
    __nv_bfloat16 h2 = __float2bfloat16(v2), h3 = __float2bfloat16(v3);
    __nv_bfloat16 hv[4] = {h0, h1, h2, h3};
    __nv_bfloat16 lv[4] = {
        __float2bfloat16(v0 - __bfloat162float(h0)),
        __float2bfloat16(v1 - __bfloat162float(h1)),
        __float2bfloat16(v2 - __bfloat162float(h2)),
        __float2bfloat16(v3 - __bfloat162float(h3))};
    *(uint2*)&g_yh[i] = *(const uint2*)hv;
    *(uint2*)&g_yl[i] = *(const uint2*)lv;
}

// ---------------- fused scatter: out = dir0(tmp0) + dir1(tmp1), single write ----------------
__global__ void k_scatter_sum(float* __restrict__ out) {
    __shared__ float t0[32][33];
    __shared__ float t1[32][33];
    int rt = blockIdx.x, ct = blockIdx.y, b = blockIdx.z;
    int tx = threadIdx.x, ty = threadIdx.y;
    int c0 = ct * 32;
    int h = rt >> 1, w0 = (rt & 1) * 32;
    int rem0 = h * 64 + w0;
    const float* tmp0 = g_tmp;
    const float* tmp1 = g_tmp + TOFF;
    #pragma unroll
    for (int i = 0; i < 4; i++) {
        int r = ty + i * 8;
        t0[r][tx] = tmp0[(size_t)(b * 4096 + rem0 + r) * CDIM + c0 + tx];
        t1[r][tx] = tmp1[(size_t)(b * 4096 + (w0 + r) * 64 + h) * CDIM + c0 + tx];
    }
    __syncthreads();
    #pragma unroll
    for (int i = 0; i < 4; i++) {
        int c = c0 + ty + i * 8;
        size_t o = (size_t)(b * 256 + c) * 4096 + rem0 + tx;
        out[o] = t0[tx][ty + i * 8] + t1[tx][ty + i * 8];
    }
}

// ---------------- launch ----------------
extern "C" void kernel_launch(void* const* d_in, const int* in_sizes, int n_in,
                              void* d_out, int out_size) {
    const float* x = (const float*)d_in[0];
    float* out = (float*)d_out;

    const float* Win0  = (const float*)d_in[1];
    const float* cw0   = (const float*)d_in[2];
    const float* cb0   = (const float*)d_in[3];
    const float* Wx0   = (const float*)d_in[4];
    const float* Wdt0  = (const float*)d_in[5];
    const float* bdt0  = (const float*)d_in[6];
    const float* Alog0 = (const float*)d_in[7];
    const float* Dp0   = (const float*)d_in[8];
    const float* Wout0 = (const float*)d_in[9];
    const float* Win1  = (const float*)d_in[10];
    const float* cw1   = (const float*)d_in[11];
    const float* cb1   = (const float*)d_in[12];
    const float* Wx1   = (const float*)d_in[13];
    const float* Wdt1  = (const float*)d_in[14];
    const float* bdt1  = (const float*)d_in[15];
    const float* Alog1 = (const float*)d_in[16];
    const float* Dp1   = (const float*)d_in[17];
    const float* Wout1 = (const float*)d_in[18];

    cudaError_t e = cudaFuncSetAttribute(k_mma_gemm32,
        cudaFuncAttributeMaxDynamicSharedMemorySize, 2 * STG32 * 2);
    bool use32 = (e == cudaSuccess);
    cudaGetLastError();

    k_transpose_hw<<<dim3(2, 2, 2048), dim3(32, 8)>>>(x);
    k_convA<<<dim3(128, 8, 16), dim3(32, 8)>>>(x);
    k_convW<<<dim3(32, 8, 2), dim3(32, 8)>>>(Win0, Win1, 256, 1024, 0);
    if (use32) {
        k_mma_gemm32<<<dim3(8, 256, 2), 256, 2 * STG32 * 2>>>(0, cw0, cb0, cw1, cb1);
    } else {
        k_mma_gemm16<<<dim3(8, 256, 2), 256>>>(0);
        k_conv_silu<<<dim3(NSEQ, 4, 2), 128>>>(cw0, cb0, cw1, cb1);
    }
    k_xproj<<<dim3(MDIM / 64, 2), 256>>>(Wx0, Wx1);
    k_scan<<<dim3(NSEQ, 2), 512>>>(Alog0, Wdt0, bdt0, Dp0, Alog1, Wdt1, bdt1, Dp1);
    k_gate<<<(2 * MDIM * DI) / 1024, 256>>>(0);
    k_convW<<<dim3(8, 16, 2), dim3(32, 8)>>>(Wout0, Wout1, 512, 256, 1);
    if (use32) k_mma_gemm32<<<dim3(2, 256, 2), 256, 2 * STG32 * 2>>>(1, nullptr, nullptr, nullptr, nullptr);
    else       k_mma_gemm16<<<dim3(2, 256, 2), 256>>>(1);
    k_scatter_sum<<<dim3(128, 8, 8), dim3(32, 8)>>>(out);
}

// round 14
// speedup vs baseline: 1.2802x; 1.0120x over previous
#include <cuda_runtime.h>
#include <cuda_bf16.h>
#include <cstdint>
#include <math.h>

// ---------------- problem constants ----------------
#define NSEQ   512
#define LSEQ   64
#define MDIM   (NSEQ*LSEQ)  // 32768
#define CDIM   256
#define DI     512
#define NXZ    1024
#define DST    16
#define DTR    16
#define NXP    48

#define AOFF   (MDIM * 256)   // per-dir A (bf16) elems
#define XOFF   (MDIM * DI)    // per-dir x/z/y elems
#define TOFF   (MDIM * CDIM)  // per-dir tmp elems
#define DBCOFF (MDIM * NXP)

// ---------------- scratch (device symbols; both dirs batched) ----------------
__device__ float g_z   [2 * XOFF];
__device__ float g_xraw[2 * XOFF];      // fallback path only
__device__ float g_xc  [2 * XOFF];
__device__ float g_dbc [2 * DBCOFF];
__device__ float g_y   [2 * XOFF];
__device__ float g_tmp [2 * TOFF];
__device__ __nv_bfloat16 g_ah [2 * AOFF];
__device__ __nv_bfloat16 g_al [2 * AOFF];
__device__ __nv_bfloat16 g_yh [2 * XOFF];
__device__ __nv_bfloat16 g_yl [2 * XOFF];
__device__ __nv_bfloat16 g_wtih[2 * 1024 * 256];
__device__ __nv_bfloat16 g_wtil[2 * 1024 * 256];
__device__ __nv_bfloat16 g_wtoh[2 * 256 * 512];
__device__ __nv_bfloat16 g_wtol[2 * 256 * 512];

__device__ __forceinline__ float siluf(float v)    { return v / (1.f + __expf(-v)); }
__device__ __forceinline__ float softplusf(float v){ return (v > 20.f) ? v : log1pf(expf(v)); }

// ---------------- mma.sync / cp.async / ldmatrix helpers ----------------
__device__ __forceinline__ void mma16816(float* c, const uint32_t* a, const uint32_t* b) {
    asm volatile(
        "mma.sync.aligned.m16n8k16.row.col.f32.bf16.bf16.f32 "
        "{%0,%1,%2,%3}, {%4,%5,%6,%7}, {%8,%9}, {%0,%1,%2,%3};\n"
        : "+f"(c[0]), "+f"(c[1]), "+f"(c[2]), "+f"(c[3])
        : "r"(a[0]), "r"(a[1]), "r"(a[2]), "r"(a[3]), "r"(b[0]), "r"(b[1]));
}
__device__ __forceinline__ void cp16(uint32_t saddr, const void* g) {
    asm volatile("cp.async.cg.shared.global [%0], [%1], 16;" :: "r"(saddr), "l"(g));
}
__device__ __forceinline__ void ldsm4(uint32_t* r, uint32_t saddr) {
    asm volatile("ldmatrix.sync.aligned.m8n8.x4.shared.b16 {%0,%1,%2,%3}, [%4];"
        : "=r"(r[0]), "=r"(r[1]), "=r"(r[2]), "=r"(r[3]) : "r"(saddr));
}
#define CP_COMMIT() asm volatile("cp.async.commit_group;" ::: "memory")
#define CP_WAIT(n)  asm volatile("cp.async.wait_group %0;" :: "n"(n) : "memory")

// ---------------- convert A (both dirs, transpose fused for dir1) ----------------
// dir0: m = b*4096 + rem, A[m][k] = x[(b*256+k)*4096 + rem]
//   block (rt, kt, b): stage s[k][rem] from coalesced rem-rows, write k-contiguous.
// dir1: m = b*4096 + w*64 + h, A[m][k] = x[(b*256+k)*4096 + h*64 + w]
//   block bx -> (h = bx>>1, wt = bx&1), kt, b: stage s[k][w] from coalesced w-rows,
//   write k-contiguous at m = b*4096 + (wt*32+wl)*64 + h.
__global__ void k_convA(const float* __restrict__ xin) {
    __shared__ float t[32][33];
    int z = blockIdx.z;            // dir*8 + b
    int dir = z >> 3, b = z & 7;
    int kt = blockIdx.y;
    int tx = threadIdx.x, ty = threadIdx.y;
    size_t dofs = (size_t)dir * AOFF;

    if (dir == 0) {
        int rt = blockIdx.x;
        #pragma unroll
        for (int i = 0; i < 4; i++) {
            int k = kt * 32 + ty + i * 8;
            t[ty + i * 8][tx] = xin[(size_t)(b * 256 + k) * 4096 + rt * 32 + tx];
        }
        __syncthreads();
        #pragma unroll
        for (int i = 0; i < 4; i++) {
            int rem = rt * 32 + ty + i * 8;
            size_t m = (size_t)b * 4096 + rem;
            float v = t[tx][ty + i * 8];
            __nv_bfloat16 h = __float2bfloat16(v);
            g_ah[dofs + m * 256 + kt * 32 + tx] = h;
            g_al[dofs + m * 256 + kt * 32 + tx] = __float2bfloat16(v - __bfloat162float(h));
        }
    } else {
        int h  = blockIdx.x >> 1;
        int wt = blockIdx.x & 1;
        #pragma unroll
        for (int i = 0; i < 4; i++) {
            int k = kt * 32 + ty + i * 8;
            t[ty + i * 8][tx] = xin[(size_t)(b * 256 + k) * 4096 + h * 64 + wt * 32 + tx];
        }
        __syncthreads();
        #pragma unroll
        for (int i = 0; i < 4; i++) {
            int wl = ty + i * 8;
            size_t m = (size_t)b * 4096 + (size_t)(wt * 32 + wl) * 64 + h;
            float v = t[tx][wl];
            __nv_bfloat16 hh = __float2bfloat16(v);
            g_ah[dofs + m * 256 + kt * 32 + tx] = hh;
            g_al[dofs + m * 256 + kt * 32 + tx] = __float2bfloat16(v - __bfloat162float(hh));
        }
    }
}

// ---------------- convert+transpose weights (both dirs) ----------------
__global__ void k_convW(const float* __restrict__ W0, const float* __restrict__ W1,
                        int R, int C, int which) {
    __shared__ float t[32][33];
    int dir = blockIdx.z;
    const float* W = dir ? W1 : W0;
    size_t dofs = (size_t)dir * R * C;
    __nv_bfloat16* Th = (which ? g_wtoh : g_wtih) + dofs;
    __nv_bfloat16* Tl = (which ? g_wtol : g_wtil) + dofs;
    int r0 = blockIdx.y * 32, c0 = blockIdx.x * 32;
    int tx = threadIdx.x, ty = threadIdx.y;
    #pragma unroll
    for (int i = 0; i < 4; i++)
        t[ty + i * 8][tx] = W[(size_t)(r0 + ty + i * 8) * C + c0 + tx];
    __syncthreads();
    #pragma unroll
    for (int i = 0; i < 4; i++) {
        float v = t[tx][ty + i * 8];
        int oc = c0 + ty + i * 8;
        __nv_bfloat16 h = __float2bfloat16(v);
        Th[(size_t)oc * R + r0 + tx] = h;
        Tl[(size_t)oc * R + r0 + tx] = __float2bfloat16(v - __bfloat162float(h));
    }
}

__device__ __forceinline__ void gemm_epilogue(float acc[4][4][4], float* Cout, int ldc,
                                              int m0, int n0, int wr, int wc, int g, int tg)
{
    #pragma unroll
    for (int mt = 0; mt < 4; mt++)
        #pragma unroll
        for (int nt = 0; nt < 4; nt++) {
            int row = m0 + wr * 64 + mt * 16 + g;
            int col = n0 + wc * 32 + nt * 8 + tg * 2;
            *(float2*)&Cout[(size_t)row * ldc + col] =
                make_float2(acc[mt][nt][0], acc[mt][nt][1]);
            *(float2*)&Cout[(size_t)(row + 8) * ldc + col] =
                make_float2(acc[mt][nt][2], acc[mt][nt][3]);
        }
}

// ---------------- HMMA bf16x3 GEMM, BK=32, cp.async 2-stage, ldmatrix, batched dirs ----------------
#define SSTR32 40
#define TILE32 (128 * SSTR32)
#define STG32  (4 * TILE32)
#define SSTG   132
__global__ void __launch_bounds__(256, 2) k_mma_gemm32(int mode,
        const float* __restrict__ cw0, const float* __restrict__ cb0,
        const float* __restrict__ cw1, const float* __restrict__ cb1) {
    extern __shared__ __nv_bfloat16 dsm[];

    int dir = blockIdx.z;
    const __nv_bfloat16 *Ah, *Al, *Bh, *Bl;
    int K;
    if (mode == 0) {
        K = 256;
        Ah = g_ah + (size_t)dir * AOFF;  Al = g_al + (size_t)dir * AOFF;
        Bh = g_wtih + (size_t)dir * 1024 * 256;
        Bl = g_wtil + (size_t)dir * 1024 * 256;
    } else {
        K = 512;
        Ah = g_yh + (size_t)dir * XOFF;  Al = g_yl + (size_t)dir * XOFF;
        Bh = g_wtoh + (size_t)dir * 256 * 512;
        Bl = g_wtol + (size_t)dir * 256 * 512;
    }

    int tid = threadIdx.x, warp = tid >> 5, lane = tid & 31;
    int wr = warp >> 2, wc = warp & 3;
    int g = lane >> 2, tg = lane & 3;
    int m0 = blockIdx.y * 128, n0 = blockIdx.x * 128;

    const __nv_bfloat16* base0 = Ah + (size_t)m0 * K;
    const __nv_bfloat16* base1 = Al + (size_t)m0 * K;
    const __nv_bfloat16* base2 = Bh + (size_t)n0 * K;
    const __nv_bfloat16* base3 = Bl + (size_t)n0 * K;

    uint32_t sbase = (uint32_t)__cvta_generic_to_shared(dsm);
    int a_row = wr * 64 + (lane & 15);
    int a_colx = (lane >> 4) << 3;
    int b_row = wc * 32 + (lane & 7) + ((lane & 16) ? 8 : 0);
    int b_colx = (lane & 8);

    float acc[4][4][4];
    #pragma unroll
    for (int i = 0; i < 4; i++)
        #pragma unroll
        for (int j = 0; j < 4; j++)
            #pragma unroll
            for (int q = 0; q < 4; q++) acc[i][j][q] = 0.f;

    #pragma unroll
    for (int i = 0; i < 2; i++) {
        int idx = tid + i * 256;
        int r = idx >> 2, q = idx & 3;
        size_t go = (size_t)r * K + q * 8;
        uint32_t so = sbase + (uint32_t)(r * SSTR32 + q * 8) * 2;
        cp16(so + 0 * TILE32 * 2, base0 + go);
        cp16(so + 1 * TILE32 * 2, base1 + go);
        cp16(so + 2 * TILE32 * 2, base2 + go);
        cp16(so + 3 * TILE32 * 2, base3 + go);
    }
    CP_COMMIT();

    const int T = K >> 5;
    for (int it = 0; it < T; it++) {
        if (it + 1 < T) {
            int k0n = (it + 1) << 5;
            uint32_t sb = sbase + ((it + 1) & 1) * STG32 * 2;
            #pragma unroll
            for (int i = 0; i < 2; i++) {
                int idx = tid + i * 256;
                int r = idx >> 2, q = idx & 3;
                size_t go = (size_t)r * K + q * 8 + k0n;
                uint32_t so = sb + (uint32_t)(r * SSTR32 + q * 8) * 2;
                cp16(so + 0 * TILE32 * 2, base0 + go);
                cp16(so + 1 * TILE32 * 2, base1 + go);
                cp16(so + 2 * TILE32 * 2, base2 + go);
                cp16(so + 3 * TILE32 * 2, base3 + go);
            }
            CP_COMMIT();
            CP_WAIT(1);
        } else {
            CP_WAIT(0);
        }
        __syncthreads();

        uint32_t st = sbase + (it & 1) * STG32 * 2;

        #pragma unroll
        for (int ks = 0; ks < 2; ks++) {
            uint32_t a_hi[4][4], a_lo[4][4], b_hi[4][2], b_lo[4][2];
            uint32_t abase = st + (uint32_t)(a_row * SSTR32 + ks * 16 + a_colx) * 2;
            #pragma unroll
            for (int mt = 0; mt < 4; mt++) {
                uint32_t off = abase + (uint32_t)(mt * 16 * SSTR32) * 2;
                ldsm4(a_hi[mt], off);
                ldsm4(a_lo[mt], off + TILE32 * 2);
            }
            uint32_t bbase = st + 2 * TILE32 * 2 +
                             (uint32_t)(b_row * SSTR32 + ks * 16 + b_colx) * 2;
            #pragma unroll
            for (int p = 0; p < 2; p++) {
                uint32_t off = bbase + (uint32_t)(p * 16 * SSTR32) * 2;
                uint32_t rb[4];
                ldsm4(rb, off);
                b_hi[2 * p][0] = rb[0]; b_hi[2 * p][1] = rb[1];
                b_hi[2 * p + 1][0] = rb[2]; b_hi[2 * p + 1][1] = rb[3];
                ldsm4(rb, off + TILE32 * 2);
                b_lo[2 * p][0] = rb[0]; b_lo[2 * p][1] = rb[1];
                b_lo[2 * p + 1][0] = rb[2]; b_lo[2 * p + 1][1] = rb[3];
            }
            #pragma unroll
            for (int mt = 0; mt < 4; mt++)
                #pragma unroll
                for (int nt = 0; nt < 4; nt++) {
                    mma16816(acc[mt][nt], a_hi[mt], b_hi[nt]);
                    mma16816(acc[mt][nt], a_hi[mt], b_lo[nt]);
                    mma16816(acc[mt][nt], a_lo[mt], b_hi[nt]);
                }
        }
        __syncthreads();
    }

    if (mode == 0) {
        if (blockIdx.x < 4) {
            float* stage = (float*)dsm;
            #pragma unroll
            for (int mt = 0; mt < 4; mt++)
                #pragma unroll
                for (int nt = 0; nt < 4; nt++) {
                    int row = wr * 64 + mt * 16 + g;
                    int col = wc * 32 + nt * 8 + tg * 2;
                    *(float2*)&stage[row * SSTG + col] =
                        make_float2(acc[mt][nt][0], acc[mt][nt][1]);
                    *(float2*)&stage[(row + 8) * SSTG + col] =
                        make_float2(acc[mt][nt][2], acc[mt][nt][3]);
                }
            __syncthreads();
            const float* cw = dir ? cw1 : cw0;
            const float* cb = dir ? cb1 : cb0;
            int dl = tid & 127;
            int sh = tid >> 7;
            int dg = n0 + dl;
            float w0 = cw[dg * 4 + 0], w1 = cw[dg * 4 + 1];
            float w2 = cw[dg * 4 + 2], w3 = cw[dg * 4 + 3];
            float bias = cb[dg];
            float x0 = 0.f, x1 = 0.f, x2 = 0.f;
            const float* sp = stage + (sh * 64) * SSTG + dl;
            float* op = g_xc + (size_t)dir * XOFF + (size_t)(m0 + sh * 64) * DI + dg;
            #pragma unroll 4
            for (int t = 0; t < LSEQ; t++) {
                float x3 = sp[t * SSTG];
                float a = fmaf(w3, x3, fmaf(w2, x2, fmaf(w1, x1, fmaf(w0, x0, bias))));
                op[t * DI] = siluf(a);
                x0 = x1; x1 = x2; x2 = x3;
            }
        } else {
            gemm_epilogue(acc, g_z + (size_t)dir * XOFF, DI, m0, n0 - 512, wr, wc, g, tg);
        }
    } else {
        gemm_epilogue(acc, g_tmp + (size_t)dir * TOFF, CDIM, m0, n0, wr, wc, g, tg);
    }
}

// ---------------- fallback: BK=16, static smem, batched dirs (no conv fusion) ----------------
#define SSTR 24
#define TILE_E (128 * SSTR)
#define STAGE_E (4 * TILE_E)
__global__ void __launch_bounds__(256, 2) k_mma_gemm16(int mode) {
    __shared__ __align__(16) __nv_bfloat16 smem[2 * STAGE_E];

    int dir = blockIdx.z;
    const __nv_bfloat16 *Ah, *Al, *Bh, *Bl;
    int K;
    if (mode == 0) {
        K = 256;
        Ah = g_ah + (size_t)dir * AOFF;  Al = g_al + (size_t)dir * AOFF;
        Bh = g_wtih + (size_t)dir * 1024 * 256;
        Bl = g_wtil + (size_t)dir * 1024 * 256;
    } else {
        K = 512;
        Ah = g_yh + (size_t)dir * XOFF;  Al = g_yl + (size_t)dir * XOFF;
        Bh = g_wtoh + (size_t)dir * 256 * 512;
        Bl = g_wtol + (size_t)dir * 256 * 512;
    }

    int tid = threadIdx.x, warp = tid >> 5, lane = tid & 31;
    int wr = warp >> 2, wc = warp & 3;
    int g = lane >> 2, tg = lane & 3;
    int m0 = blockIdx.y * 128, n0 = blockIdx.x * 128;

    const __nv_bfloat16* base0 = Ah + (size_t)m0 * K;
    const __nv_bfloat16* base1 = Al + (size_t)m0 * K;
    const __nv_bfloat16* base2 = Bh + (size_t)n0 * K;
    const __nv_bfloat16* base3 = Bl + (size_t)n0 * K;

    uint32_t sbase = (uint32_t)__cvta_generic_to_shared(smem);
    int lr = tid >> 1, lq = tid & 1;
    size_t goff = (size_t)lr * K + lq * 8;
    uint32_t soff = (uint32_t)(lr * SSTR + lq * 8) * 2;

    float acc[4][4][4];
    #pragma unroll
    for (int i = 0; i < 4; i++)
        #pragma unroll
        for (int j = 0; j < 4; j++)
            #pragma unroll
            for (int q = 0; q < 4; q++) acc[i][j][q] = 0.f;

    {
        uint32_t sb = sbase + soff;
        cp16(sb + 0 * TILE_E * 2, base0 + goff);
        cp16(sb + 1 * TILE_E * 2, base1 + goff);
        cp16(sb + 2 * TILE_E * 2, base2 + goff);
        cp16(sb + 3 * TILE_E * 2, base3 + goff);
        CP_COMMIT();
    }

    const int T = K >> 4;
    for (int it = 0; it < T; it++) {
        if (it + 1 < T) {
            int k0n = (it + 1) << 4;
            uint32_t sb = sbase + ((it + 1) & 1) * STAGE_E * 2 + soff;
            cp16(sb + 0 * TILE_E * 2, base0 + goff + k0n);
            cp16(sb + 1 * TILE_E * 2, base1 + goff + k0n);
            cp16(sb + 2 * TILE_E * 2, base2 + goff + k0n);
            cp16(sb + 3 * TILE_E * 2, base3 + goff + k0n);
            CP_COMMIT();
            CP_WAIT(1);
        } else {
            CP_WAIT(0);
        }
        __syncthreads();

        const __nv_bfloat16* s0 = smem + (it & 1) * STAGE_E;
        const __nv_bfloat16* sAh = s0;
        const __nv_bfloat16* sAl = s0 + TILE_E;
        const __nv_bfloat16* sBh = s0 + 2 * TILE_E;
        const __nv_bfloat16* sBl = s0 + 3 * TILE_E;
        int kb = tg * 2;

        uint32_t a_hi[4][4], a_lo[4][4], b_hi[4][2], b_lo[4][2];
        #pragma unroll
        for (int mt = 0; mt < 4; mt++) {
            int row = wr * 64 + mt * 16 + g;
            a_hi[mt][0] = *(const uint32_t*)&sAh[row * SSTR + kb];
            a_hi[mt][1] = *(const uint32_t*)&sAh[(row + 8) * SSTR + kb];
            a_hi[mt][2] = *(const uint32_t*)&sAh[row * SSTR + kb + 8];
            a_hi[mt][3] = *(const uint32_t*)&sAh[(row + 8) * SSTR + kb + 8];
            a_lo[mt][0] = *(const uint32_t*)&sAl[row * SSTR + kb];
            a_lo[mt][1] = *(const uint32_t*)&sAl[(row + 8) * SSTR + kb];
            a_lo[mt][2] = *(const uint32_t*)&sAl[row * SSTR + kb + 8];
            a_lo[mt][3] = *(const uint32_t*)&sAl[(row + 8) * SSTR + kb + 8];
        }
        #pragma unroll
        for (int nt = 0; nt < 4; nt++) {
            int rn = wc * 32 + nt * 8 + g;
            b_hi[nt][0] = *(const uint32_t*)&sBh[rn * SSTR + kb];
            b_hi[nt][1] = *(const uint32_t*)&sBh[rn * SSTR + kb + 8];
            b_lo[nt][0] = *(const uint32_t*)&sBl[rn * SSTR + kb];
            b_lo[nt][1] = *(const uint32_t*)&sBl[rn * SSTR + kb + 8];
        }
        #pragma unroll
        for (int mt = 0; mt < 4; mt++)
            #pragma unroll
            for (int nt = 0; nt < 4; nt++) {
                mma16816(acc[mt][nt], a_hi[mt], b_hi[nt]);
                mma16816(acc[mt][nt], a_hi[mt], b_lo[nt]);
                mma16816(acc[mt][nt], a_lo[mt], b_hi[nt]);
            }
        __syncthreads();
    }
    if (mode == 0) {
        if (blockIdx.x < 4) gemm_epilogue(acc, g_xraw + (size_t)dir * XOFF, DI, m0, n0, wr, wc, g, tg);
        else                gemm_epilogue(acc, g_z + (size_t)dir * XOFF, DI, m0, n0 - 512, wr, wc, g, tg);
    } else {
        gemm_epilogue(acc, g_tmp + (size_t)dir * TOFF, CDIM, m0, n0, wr, wc, g, tg);
    }
}

// ---------------- conv+silu (FALLBACK path only), batched dirs ----------------
__global__ void k_conv_silu(const float* __restrict__ cw0, const float* __restrict__ cb0,
                            const float* __restrict__ cw1, const float* __restrict__ cb1) {
    int dir = blockIdx.z;
    const float* cw = dir ? cw1 : cw0;
    const float* cb = dir ? cb1 : cb0;
    int s = blockIdx.x;
    int d = blockIdx.y * 128 + threadIdx.x;
    float w0 = cw[d * 4 + 0], w1 = cw[d * 4 + 1], w2 = cw[d * 4 + 2], w3 = cw[d * 4 + 3];
    float bias = cb[d];
    float x0 = 0.f, x1 = 0.f, x2 = 0.f;
    const float* xp = g_xraw + (size_t)dir * XOFF + (size_t)s * LSEQ * DI + d;
    float*       op = g_xc   + (size_t)dir * XOFF + (size_t)s * LSEQ * DI + d;
    #pragma unroll 4
    for (int t = 0; t < LSEQ; t++) {
        float x3 = xp[t * DI];
        float a = fmaf(w3, x3, fmaf(w2, x2, fmaf(w1, x1, fmaf(w0, x0, bias))));
        op[t * DI] = siluf(a);
        x0 = x1; x1 = x2; x2 = x3;
    }
}

// ---------------- x-proj GEMM, batched dirs ----------------
__global__ void __launch_bounds__(256) k_xproj(const float* __restrict__ Wx0,
                                               const float* __restrict__ Wx1) {
    __shared__ __align__(16) float As[32][68];
    __shared__ float Bs[32][48];
    int dir = blockIdx.y;
    const float* Wx = dir ? Wx1 : Wx0;
    const float* xc = g_xc + (size_t)dir * XOFF;
    float* dbc = g_dbc + (size_t)dir * DBCOFF;
    int m0 = blockIdx.x * 64;
    int tid = threadIdx.x;
    int rg = tid & 15;
    int cg = tid >> 4;
    float acc[4][3];
    #pragma unroll
    for (int i = 0; i < 4; i++)
        #pragma unroll
        for (int j = 0; j < 3; j++) acc[i][j] = 0.f;

    for (int k0 = 0; k0 < DI; k0 += 32) {
        #pragma unroll
        for (int i = 0; i < 2; i++) {
            int idx = tid + i * 256;
            int r = idx >> 3, kc = (idx & 7) * 4;
            float4 v = *(const float4*)&xc[(size_t)(m0 + r) * DI + k0 + kc];
            As[kc + 0][r] = v.x; As[kc + 1][r] = v.y;
            As[kc + 2][r] = v.z; As[kc + 3][r] = v.w;
        }
        #pragma unroll
        for (int i = 0; i < 6; i++) {
            int idx = tid + i * 256;
            int k = idx / 48, n = idx % 48;
            Bs[k][n] = Wx[(k0 + k) * NXP + n];
        }
        __syncthreads();
        #pragma unroll
        for (int k = 0; k < 32; k++) {
            float4 a = *(const float4*)&As[k][rg * 4];
            float b0 = Bs[k][cg * 3 + 0];
            float b1 = Bs[k][cg * 3 + 1];
            float b2 = Bs[k][cg * 3 + 2];
            acc[0][0] = fmaf(a.x, b0, acc[0][0]);
            acc[0][1] = fmaf(a.x, b1, acc[0][1]);
            acc[0][2] = fmaf(a.x, b2, acc[0][2]);
            acc[1][0] = fmaf(a.y, b0, acc[1][0]);
            acc[1][1] = fmaf(a.y, b1, acc[1][1]);
            acc[1][2] = fmaf(a.y, b2, acc[1][2]);
            acc[2][0] = fmaf(a.z, b0, acc[2][0]);
            acc[2][1] = fmaf(a.z, b1, acc[2][1]);
            acc[2][2] = fmaf(a.z, b2, acc[2][2]);
            acc[3][0] = fmaf(a.w, b0, acc[3][0]);
            acc[3][1] = fmaf(a.w, b1, acc[3][1]);
            acc[3][2] = fmaf(a.w, b2, acc[3][2]);
        }
        __syncthreads();
    }
    #pragma unroll
    for (int i = 0; i < 4; i++)
        #pragma unroll
        for (int j = 0; j < 3; j++)
            dbc[(size_t)(m0 + rg * 4 + i) * NXP + cg * 3 + j] = acc[i][j];
}

// ---------------- selective scan, batched dirs ----------------
__global__ void __launch_bounds__(512) k_scan(
    const float* __restrict__ Alog0, const float* __restrict__ Wdt0,
    const float* __restrict__ bdt0,  const float* __restrict__ Dp0,
    const float* __restrict__ Alog1, const float* __restrict__ Wdt1,
    const float* __restrict__ bdt1,  const float* __restrict__ Dp1) {
    __shared__ float Rs[LSEQ][DTR];
    __shared__ float Bs[LSEQ][DST];
    __shared__ float Cs[LSEQ][DST];
    int dir = blockIdx.y;
    const float* Alog = dir ? Alog1 : Alog0;
    const float* Wdt  = dir ? Wdt1  : Wdt0;
    const float* bdt  = dir ? bdt1  : bdt0;
    const float* Dp   = dir ? Dp1   : Dp0;
    const float* dbc  = g_dbc + (size_t)dir * DBCOFF;
    int s = blockIdx.x;
    int d = threadIdx.x;
    for (int i = threadIdx.x; i < LSEQ * NXP; i += 512) {
        int t = i / NXP, j = i % NXP;
        float v = dbc[(size_t)(s * LSEQ + t) * NXP + j];
        if (j < DTR) Rs[t][j] = v;
        else if (j < DTR + DST) Bs[t][j - DTR] = v;
        else Cs[t][j - DTR - DST] = v;
    }
    __syncthreads();
    float A[DST], h[DST], w[DTR];
    bool fast = true;
    #pragma unroll
    for (int n = 0; n < DST; n++) {
        A[n] = -expf(Alog[d * DST + n]);
        h[n] = 0.f;
        fast = fast && (fabsf(A[n] + (float)(n + 1)) <= 1e-3f * (float)(n + 1));
    }
    #pragma unroll
    for (int i = 0; i < DTR; i++) w[i] = Wdt[i * DI + d];
    float bd = bdt[d];
    float Dd = Dp[d];
    const float* xp = g_xc + (size_t)dir * XOFF + (size_t)s * LSEQ * DI + d;
    float*       yp = g_y  + (size_t)dir * XOFF + (size_t)s * LSEQ * DI + d;

    if (fast) {
        for (int t = 0; t < LSEQ; t++) {
            float acc = bd;
            #pragma unroll
            for (int i = 0; i < DTR; i++) acc = fmaf(Rs[t][i], w[i], acc);
            float dt = softplusf(acc);
            float xc = xp[t * DI];
            float dtx = dt * xc;
            float r = __expf(-dt);
            float y = 0.f, p = 1.f;
            #pragma unroll
            for (int n = 0; n < DST; n++) {
                p *= r;
                h[n] = fmaf(p, h[n], dtx * Bs[t][n]);
                y = fmaf(h[n], Cs[t][n], y);
            }
            yp[t * DI] = fmaf(xc, Dd, y);
        }
    } else {
        for (int t = 0; t < LSEQ; t++) {
            float acc = bd;
            #pragma unroll
            for (int i = 0; i < DTR; i++) acc = fmaf(Rs[t][i], w[i], acc);
            float dt = softplusf(acc);
            float xc = xp[t * DI];
            float dtx = dt * xc;
            float y = 0.f;
            #pragma unroll
            for (int n = 0; n < DST; n++) {
                float dA = __expf(dt * A[n]);
                h[n] = fmaf(dA, h[n], dtx * Bs[t][n]);
                y = fmaf(h[n], Cs[t][n], y);
            }
            yp[t * DI] = fmaf(xc, Dd, y);
        }
    }
}

// ---------------- gate: both dirs linear ----------------
__global__ void k_gate(int dummy) {
    size_t i = ((size_t)blockIdx.x * 256 + threadIdx.x) * 4;
    float4 y = *(const float4*)&g_y[i];
    float4 z = *(const float4*)&g_z[i];
    float v0 = y.x * siluf(z.x);
    float v1 = y.y * siluf(z.y);
    float v2 = y.z * siluf(z.z);
    float v3 = y.w * siluf(z.w);
    __nv_bfloat16 h0 = __float2bfloat16(v0), h1 = __float2bfloat16(v1);
    __nv_bfloat16 h2 = __float2bfloat16(v2), h3 = __float2bfloat16(v3);
    __nv_bfloat16 hv[4] = {h0, h1, h2, h3};
    __nv_bfloat16 lv[4] = {
        __float2bfloat16(v0 - __bfloat162float(h0)),
        __float2bfloat16(v1 - __bfloat162float(h1)),
        __float2bfloat16(v2 - __bfloat162float(h2)),
        __float2bfloat16(v3 - __bfloat162float(h3))};
    *(uint2*)&g_yh[i] = *(const uint2*)hv;
    *(uint2*)&g_yl[i] = *(const uint2*)lv;
}

// ---------------- fused scatter: out = dir0(tmp0) + dir1(tmp1), single write ----------------
__global__ void k_scatter_sum(float* __restrict__ out) {
    __shared__ float t0[32][33];
    __shared__ float t1[32][33];
    int rt = blockIdx.x, ct = blockIdx.y, b = blockIdx.z;
    int tx = threadIdx.x, ty = threadIdx.y;
    int c0 = ct * 32;
    int h = rt >> 1, w0 = (rt & 1) * 32;
    int rem0 = h * 64 + w0;
    const float* tmp0 = g_tmp;
    const float* tmp1 = g_tmp + TOFF;
    #pragma unroll
    for (int i = 0; i < 4; i++) {
        int r = ty + i * 8;
        t0[r][tx] = tmp0[(size_t)(b * 4096 + rem0 + r) * CDIM + c0 + tx];
        t1[r][tx] = tmp1[(size_t)(b * 4096 + (w0 + r) * 64 + h) * CDIM + c0 + tx];
    }
    __syncthreads();
    #pragma unroll
    for (int i = 0; i < 4; i++) {
        int c = c0 + ty + i * 8;
        size_t o = (size_t)(b * 256 + c) * 4096 + rem0 + tx;
        out[o] = t0[tx][ty + i * 8] + t1[tx][ty + i * 8];
    }
}

// ---------------- launch ----------------
extern "C" void kernel_launch(void* const* d_in, const int* in_sizes, int n_in,
                              void* d_out, int out_size) {
    const float* x = (const float*)d_in[0];
    float* out = (float*)d_out;

    const float* Win0  = (const float*)d_in[1];
    const float* cw0   = (const float*)d_in[2];
    const float* cb0   = (const float*)d_in[3];
    const float* Wx0   = (const float*)d_in[4];
    const float* Wdt0  = (const float*)d_in[5];
    const float* bdt0  = (const float*)d_in[6];
    const float* Alog0 = (const float*)d_in[7];
    const float* Dp0   = (const float*)d_in[8];
    const float* Wout0 = (const float*)d_in[9];
    const float* Win1  = (const float*)d_in[10];
    const float* cw1   = (const float*)d_in[11];
    const float* cb1   = (const float*)d_in[12];
    const float* Wx1   = (const float*)d_in[13];
    const float* Wdt1  = (const float*)d_in[14];
    const float* bdt1  = (const float*)d_in[15];
    const float* Alog1 = (const float*)d_in[16];
    const float* Dp1   = (const float*)d_in[17];
    const float* Wout1 = (const float*)d_in[18];

    cudaError_t e = cudaFuncSetAttribute(k_mma_gemm32,
        cudaFuncAttributeMaxDynamicSharedMemorySize, 2 * STG32 * 2);
    bool use32 = (e == cudaSuccess);
    cudaGetLastError();

    k_convA<<<dim3(128, 8, 16), dim3(32, 8)>>>(x);
    k_convW<<<dim3(32, 8, 2), dim3(32, 8)>>>(Win0, Win1, 256, 1024, 0);
    if (use32) {
        k_mma_gemm32<<<dim3(8, 256, 2), 256, 2 * STG32 * 2>>>(0, cw0, cb0, cw1, cb1);
    } else {
        k_mma_gemm16<<<dim3(8, 256, 2), 256>>>(0);
        k_conv_silu<<<dim3(NSEQ, 4, 2), 128>>>(cw0, cb0, cw1, cb1);
    }
    k_xproj<<<dim3(MDIM / 64, 2), 256>>>(Wx0, Wx1);
    k_scan<<<dim3(NSEQ, 2), 512>>>(Alog0, Wdt0, bdt0, Dp0, Alog1, Wdt1, bdt1, Dp1);
    k_gate<<<(2 * MDIM * DI) / 1024, 256>>>(0);
    k_convW<<<dim3(8, 16, 2), dim3(32, 8)>>>(Wout0, Wout1, 512, 256, 1);
    if (use32) k_mma_gemm32<<<dim3(2, 256, 2), 256, 2 * STG32 * 2>>>(1, nullptr, nullptr, nullptr, nullptr);
    else       k_mma_gemm16<<<dim3(2, 256, 2), 256>>>(1);
    k_scatter_sum<<<dim3(128, 8, 8), dim3(32, 8)>>>(out);
}